// round 3
// baseline (speedup 1.0000x reference)
#include <cuda_runtime.h>
#include <math.h>

#define N_ 32
#define C_ 512
#define P_ 1024
#define K_ 64
#define ALPHAF 100.0f
#define EPSF 1e-12f

typedef unsigned long long u64;

__device__ __forceinline__ u64 pack2(float lo, float hi) {
    u64 r;
    asm("mov.b64 %0, {%1, %2};" : "=l"(r) : "f"(lo), "f"(hi));
    return r;
}
__device__ __forceinline__ void unpack2(u64 v, float& lo, float& hi) {
    asm("mov.b64 {%0, %1}, %2;" : "=f"(lo), "=f"(hi) : "l"(v));
}
__device__ __forceinline__ void fma2(u64& d, u64 a, u64 b) {
    asm("fma.rn.f32x2 %0, %1, %2, %0;" : "+l"(d) : "l"(a), "l"(b));
}

// Scratch (device globals; no allocations allowed)
__device__ float g_invn[N_ * P_];
__device__ float g_bias[K_];
__device__ float g_assign[(size_t)N_ * P_ * K_];  // [n][p][k]
__device__ float g_asum[N_ * K_];
__device__ float g_nss[N_];

// ---------------------------------------------------------------------------
// K0: inv-norm per (n,p), float4 over p. grid 32 x 256 threads = 8192 threads
// each owning 4 p-columns. Block 0 also computes bias; 1,2 zero scratch.
// ---------------------------------------------------------------------------
__global__ __launch_bounds__(256) void k0_prep(const float* __restrict__ x,
                                               const float* __restrict__ vocabs) {
    int g4 = blockIdx.x * 256 + threadIdx.x;   // 8192 = N*P/4
    int n = g4 >> 8;                           // 256 float4 per n
    int p4 = g4 & 255;
    const float4* xp = (const float4*)(x + (size_t)n * C_ * P_) + p4;
    float4 ss = make_float4(0.f, 0.f, 0.f, 0.f);
#pragma unroll 8
    for (int c = 0; c < C_; c++) {
        float4 v = xp[(size_t)c * (P_ / 4)];
        ss.x = fmaf(v.x, v.x, ss.x);
        ss.y = fmaf(v.y, v.y, ss.y);
        ss.z = fmaf(v.z, v.z, ss.z);
        ss.w = fmaf(v.w, v.w, ss.w);
    }
    float4 o;
    o.x = 1.0f / fmaxf(sqrtf(ss.x), EPSF);
    o.y = 1.0f / fmaxf(sqrtf(ss.y), EPSF);
    o.z = 1.0f / fmaxf(sqrtf(ss.z), EPSF);
    o.w = 1.0f / fmaxf(sqrtf(ss.w), EPSF);
    ((float4*)g_invn)[g4] = o;

    if (blockIdx.x == 0) {
        int lane = threadIdx.x & 31;
        int w = threadIdx.x >> 5;
#pragma unroll
        for (int r = 0; r < 8; r++) {
            int k = w * 8 + r;
            float s = 0.0f;
#pragma unroll
            for (int j = 0; j < 16; j++) {
                float v = vocabs[k * C_ + lane + 32 * j];
                s = fmaf(v, v, s);
            }
#pragma unroll
            for (int o2 = 16; o2; o2 >>= 1) s += __shfl_xor_sync(0xffffffffu, s, o2);
            if (lane == 0) g_bias[k] = -ALPHAF * sqrtf(s);
        }
    } else if (blockIdx.x == 1) {
#pragma unroll
        for (int i = 0; i < 8; i++) g_asum[threadIdx.x + 256 * i] = 0.0f;
    } else if (blockIdx.x == 2) {
        if (threadIdx.x < N_) g_nss[threadIdx.x] = 0.0f;
    }
}

// ---------------------------------------------------------------------------
// K1: logits GEMM (K=64 x Ptile=64 over C) + bias + softmax over K.
// grid (16, 32). 256 threads: thread (tx,ty) owns 8k x 2p; acc packed over k.
// ---------------------------------------------------------------------------
#define WS_STRIDE 68
#define LS_STRIDE 65

__global__ __launch_bounds__(256) void k1_assign(const float* __restrict__ x,
                                                 const float* __restrict__ vocabs) {
    __shared__ float sm[32 * WS_STRIDE + 32 * 64];
    float* ws = sm;                    // [32][WS_STRIDE]  w^T: [c][k]
    float* xs = sm + 32 * WS_STRIDE;   // [32][64]         [c][p]

    int t = threadIdx.x;
    int tx = t & 31, ty = t >> 5;
    int n = blockIdx.y;
    int p0 = blockIdx.x * 64;
    int k0 = ty * 8;
    int pl = tx * 2;

    u64 accp[4][2];
#pragma unroll
    for (int i = 0; i < 4; i++) { accp[i][0] = 0ULL; accp[i][1] = 0ULL; }

    const float* xb = x + (size_t)n * C_ * P_ + p0;

    for (int c0 = 0; c0 < C_; c0 += 32) {
#pragma unroll
        for (int i = 0; i < 8; i++) {
            int e = t + 256 * i;
            int k = e >> 5, c = e & 31;
            ws[c * WS_STRIDE + k] = (2.0f * ALPHAF) * vocabs[k * C_ + c0 + c];
        }
#pragma unroll
        for (int i = 0; i < 8; i++) {
            int e = t + 256 * i;
            int c = e >> 6, p = e & 63;
            xs[c * 64 + p] = xb[(size_t)(c0 + c) * P_ + p];
        }
        __syncthreads();
#pragma unroll
        for (int cc = 0; cc < 32; cc++) {
            ulonglong2 w01 = *(const ulonglong2*)(ws + cc * WS_STRIDE + k0);
            ulonglong2 w23 = *(const ulonglong2*)(ws + cc * WS_STRIDE + k0 + 4);
            float2 b = *(const float2*)(xs + cc * 64 + pl);
            u64 bx = pack2(b.x, b.x);
            u64 by = pack2(b.y, b.y);
            fma2(accp[0][0], w01.x, bx); fma2(accp[0][1], w01.x, by);
            fma2(accp[1][0], w01.y, bx); fma2(accp[1][1], w01.y, by);
            fma2(accp[2][0], w23.x, bx); fma2(accp[2][1], w23.x, by);
            fma2(accp[3][0], w23.y, bx); fma2(accp[3][1], w23.y, by);
        }
        __syncthreads();
    }

    // unpack
    float acc[8][2];
#pragma unroll
    for (int i = 0; i < 4; i++) {
        unpack2(accp[i][0], acc[2 * i][0], acc[2 * i + 1][0]);
        unpack2(accp[i][1], acc[2 * i][1], acc[2 * i + 1][1]);
    }

    float inv0 = g_invn[n * P_ + p0 + pl];
    float inv1 = g_invn[n * P_ + p0 + pl + 1];
    float* ls = sm;  // [64][LS_STRIDE]
#pragma unroll
    for (int i = 0; i < 8; i++) {
        float b = g_bias[k0 + i];
        ls[(pl + 0) * LS_STRIDE + k0 + i] = fmaf(acc[i][0], inv0, b);
        ls[(pl + 1) * LS_STRIDE + k0 + i] = fmaf(acc[i][1], inv1, b);
    }
    __syncthreads();

    if (t < 64) {
        float m = -1e30f;
#pragma unroll
        for (int k = 0; k < 64; k++) m = fmaxf(m, ls[t * LS_STRIDE + k]);
        float s = 0.0f;
#pragma unroll
        for (int k = 0; k < 64; k++) {
            float e = __expf(ls[t * LS_STRIDE + k] - m);
            ls[t * LS_STRIDE + k] = e;
            s += e;
        }
        float r = 1.0f / s;
        float* gp = g_assign + ((size_t)n * P_ + p0 + t) * K_;
#pragma unroll
        for (int k = 0; k < 64; k += 4) {
            float4 o;
            o.x = ls[t * LS_STRIDE + k + 0] * r;
            o.y = ls[t * LS_STRIDE + k + 1] * r;
            o.z = ls[t * LS_STRIDE + k + 2] * r;
            o.w = ls[t * LS_STRIDE + k + 3] * r;
            ls[t * LS_STRIDE + k + 0] = o.x;
            ls[t * LS_STRIDE + k + 1] = o.y;
            ls[t * LS_STRIDE + k + 2] = o.z;
            ls[t * LS_STRIDE + k + 3] = o.w;
            *(float4*)(gp + k) = o;
        }
    }
    __syncthreads();

    if (t < 64) {
        float s = 0.0f;
#pragma unroll
        for (int r2 = 0; r2 < 64; r2++) s += ls[r2 * LS_STRIDE + t];
        atomicAdd(&g_asum[n * K_ + t], s);
    }
}

// ---------------------------------------------------------------------------
// K2: vlad GEMM  out[n,k,c] = sum_p (a*invn)[p][k] * x[c][p] - asum[k]*vocab[k][c]
// grid (8, 32). thread owns 8k x 2c; acc packed over k.
// ---------------------------------------------------------------------------
#define XS2_STRIDE 66

__global__ __launch_bounds__(256) void k2_vlad(const float* __restrict__ x,
                                               const float* __restrict__ vocabs,
                                               float* __restrict__ out) {
    __shared__ float as_[32 * 64];          // [p][k]
    __shared__ float xs[32 * XS2_STRIDE];   // [p][c]

    int t = threadIdx.x;
    int tx = t & 31, ty = t >> 5;
    int n = blockIdx.y;
    int c0 = blockIdx.x * 64;
    int k0 = ty * 8;
    int cl = tx * 2;

    u64 accp[4][2];
#pragma unroll
    for (int i = 0; i < 4; i++) { accp[i][0] = 0ULL; accp[i][1] = 0ULL; }

    const float* xb = x + (size_t)n * C_ * P_;
    const float* ab = g_assign + (size_t)n * P_ * K_;
    const float* ib = g_invn + n * P_;

    for (int p0 = 0; p0 < P_; p0 += 32) {
        const float4* a4 = (const float4*)(ab + (size_t)p0 * K_);
#pragma unroll
        for (int i = 0; i < 2; i++) {
            int e4 = t + 256 * i;
            int p = e4 >> 4;
            float4 v = a4[e4];
            float inv = ib[p0 + p];
            v.x *= inv; v.y *= inv; v.z *= inv; v.w *= inv;
            *(float4*)(as_ + e4 * 4) = v;
        }
#pragma unroll
        for (int i = 0; i < 8; i++) {
            int e = t + 256 * i;
            int c = e >> 5, p = e & 31;
            xs[p * XS2_STRIDE + c] = xb[(size_t)(c0 + c) * P_ + p0 + p];
        }
        __syncthreads();
#pragma unroll
        for (int pp = 0; pp < 32; pp++) {
            ulonglong2 a01 = *(const ulonglong2*)(as_ + pp * 64 + k0);
            ulonglong2 a23 = *(const ulonglong2*)(as_ + pp * 64 + k0 + 4);
            float2 b = *(const float2*)(xs + pp * XS2_STRIDE + cl);
            u64 bx = pack2(b.x, b.x);
            u64 by = pack2(b.y, b.y);
            fma2(accp[0][0], a01.x, bx); fma2(accp[0][1], a01.x, by);
            fma2(accp[1][0], a01.y, bx); fma2(accp[1][1], a01.y, by);
            fma2(accp[2][0], a23.x, bx); fma2(accp[2][1], a23.x, by);
            fma2(accp[3][0], a23.y, bx); fma2(accp[3][1], a23.y, by);
        }
        __syncthreads();
    }

    float acc[8][2];
#pragma unroll
    for (int i = 0; i < 4; i++) {
        unpack2(accp[i][0], acc[2 * i][0], acc[2 * i + 1][0]);
        unpack2(accp[i][1], acc[2 * i][1], acc[2 * i + 1][1]);
    }

#pragma unroll
    for (int i = 0; i < 8; i++) {
        int k = k0 + i;
        float s = g_asum[n * K_ + k];
        float v0 = vocabs[k * C_ + c0 + cl];
        float v1 = vocabs[k * C_ + c0 + cl + 1];
        float2 o;
        o.x = fmaf(-s, v0, acc[i][0]);
        o.y = fmaf(-s, v1, acc[i][1]);
        *(float2*)(out + (size_t)n * (K_ * C_) + (size_t)k * C_ + c0 + cl) = o;
    }
}

// ---------------------------------------------------------------------------
// K3a: intra-normalize each [n,k,:] row, accumulate per-n sumsq.
// ---------------------------------------------------------------------------
__global__ __launch_bounds__(256) void k3a_intra(float* __restrict__ out) {
    int n = blockIdx.y, k = blockIdx.x, t = threadIdx.x;
    float* row = out + (size_t)n * (K_ * C_) + (size_t)k * C_;
    float2 v = *(float2*)(row + t * 2);
    float ss = v.x * v.x + v.y * v.y;
#pragma unroll
    for (int o = 16; o; o >>= 1) ss += __shfl_xor_sync(0xffffffffu, ss, o);
    __shared__ float wsum[8];
    if ((t & 31) == 0) wsum[t >> 5] = ss;
    __syncthreads();
    float tot = wsum[0] + wsum[1] + wsum[2] + wsum[3] +
                wsum[4] + wsum[5] + wsum[6] + wsum[7];
    float rinv = 1.0f / fmaxf(sqrtf(tot), EPSF);
    v.x *= rinv; v.y *= rinv;
    *(float2*)(row + t * 2) = v;
    if (t == 0) atomicAdd(&g_nss[n], tot * rinv * rinv);
}

// ---------------------------------------------------------------------------
// K3b: final global normalization per n (in place).
// ---------------------------------------------------------------------------
__global__ __launch_bounds__(256) void k3b_final(float* __restrict__ out) {
    int g4 = blockIdx.x * 256 + threadIdx.x;
    int n = (g4 * 4) >> 15;
    float r = 1.0f / fmaxf(sqrtf(g_nss[n]), EPSF);
    float4 v = ((float4*)out)[g4];
    v.x *= r; v.y *= r; v.z *= r; v.w *= r;
    ((float4*)out)[g4] = v;
}

// ---------------------------------------------------------------------------
extern "C" void kernel_launch(void* const* d_in, const int* in_sizes, int n_in,
                              void* d_out, int out_size) {
    const float* x = (const float*)d_in[0];
    const float* vocabs = (const float*)d_in[1];
    if (n_in >= 2 && in_sizes[0] == K_ * C_ && in_sizes[1] == N_ * C_ * P_) {
        vocabs = (const float*)d_in[0];
        x = (const float*)d_in[1];
    }
    float* out = (float*)d_out;

    k0_prep<<<32, 256>>>(x, vocabs);
    k1_assign<<<dim3(16, 32), 256>>>(x, vocabs);
    k2_vlad<<<dim3(8, 32), 256>>>(x, vocabs, out);
    k3a_intra<<<dim3(64, 32), 256>>>(out);
    k3b_final<<<1024, 256>>>(out);
}

// round 7
// speedup vs baseline: 1.4043x; 1.4043x over previous
#include <cuda_runtime.h>
#include <cuda_fp16.h>
#include <cuda_bf16.h>
#include <math.h>

#define N_ 32
#define C_ 512
#define P_ 1024
#define K_ 64
#define ALPHAF 100.0f
#define EPSF 1e-12f
#define MSCALE 2048.0f
#define INV_MSCALE 4.8828125e-4f

typedef unsigned int u32;
typedef unsigned short u16;

// ---------------- scratch ---------------------------------------------------
__device__ float g_invn[N_ * P_];
__device__ float g_bias[K_];
__device__ float g_asum[N_ * K_];
__device__ float g_nss[N_];
__device__ u32 g_x12[(size_t)N_ * C_ * P_];   // packed {fp16 h, fp16 m*2048} of x
__device__ u32 g_w12[K_ * C_];                // packed {h, m*2048} of 2*alpha*vocab
__device__ u16 g_abf[(size_t)N_ * K_ * P_];   // bf16 of a*invn  (bf16 range avoids underflow)

// ---------------- helpers ----------------------------------------------------
__device__ __forceinline__ u32 smem_u32(const void* p) {
    u32 a;
    asm("{ .reg .u64 t; cvta.to.shared.u64 t, %1; cvt.u32.u64 %0, t; }" : "=r"(a) : "l"(p));
    return a;
}
__device__ __forceinline__ u32 split_pack_s(float v) {  // h + scaled residual
    __half h = __float2half_rn(v);
    __half m = __float2half_rn((v - __half2float(h)) * MSCALE);
    return (u32)__half_as_ushort(h) | ((u32)__half_as_ushort(m) << 16);
}
__device__ __forceinline__ u16 h2bf(u16 hbits) {  // fp16 bits -> bf16 bits
    return __bfloat16_as_ushort(
        __float2bfloat16(__half2float(__ushort_as_half(hbits))));
}
__device__ __forceinline__ void ldsm4(u32* r, u32 addr) {
    asm volatile("ldmatrix.sync.aligned.m8n8.x4.shared.b16 {%0,%1,%2,%3}, [%4];"
                 : "=r"(r[0]), "=r"(r[1]), "=r"(r[2]), "=r"(r[3]) : "r"(addr));
}
__device__ __forceinline__ void ldsm4t(u32* r, u32 addr) {
    asm volatile("ldmatrix.sync.aligned.m8n8.x4.trans.shared.b16 {%0,%1,%2,%3}, [%4];"
                 : "=r"(r[0]), "=r"(r[1]), "=r"(r[2]), "=r"(r[3]) : "r"(addr));
}
__device__ __forceinline__ void mma16816(float* d, const u32* a, const u32* b) {
    asm volatile(
        "mma.sync.aligned.m16n8k16.row.col.f32.f16.f16.f32 "
        "{%0,%1,%2,%3}, {%4,%5,%6,%7}, {%8,%9}, {%0,%1,%2,%3};"
        : "+f"(d[0]), "+f"(d[1]), "+f"(d[2]), "+f"(d[3])
        : "r"(a[0]), "r"(a[1]), "r"(a[2]), "r"(a[3]), "r"(b[0]), "r"(b[1]));
}
__device__ __forceinline__ void mma16816bf(float* d, const u32* a, const u32* b) {
    asm volatile(
        "mma.sync.aligned.m16n8k16.row.col.f32.bf16.bf16.f32 "
        "{%0,%1,%2,%3}, {%4,%5,%6,%7}, {%8,%9}, {%0,%1,%2,%3};"
        : "+f"(d[0]), "+f"(d[1]), "+f"(d[2]), "+f"(d[3])
        : "r"(a[0]), "r"(a[1]), "r"(a[2]), "r"(a[3]), "r"(b[0]), "r"(b[1]));
}

// ---------------------------------------------------------------------------
// K0: scaled 2-plane split of x, inv-norm per (n,p); block 0 splits w + bias;
// block 1 zeros asum/nss.
// ---------------------------------------------------------------------------
__global__ __launch_bounds__(256) void k0_prep(const float* __restrict__ x,
                                               const float* __restrict__ vocabs) {
    int g = blockIdx.x * 256 + threadIdx.x;   // 32768 = N*P
    int n = g >> 10, p = g & 1023;
    const float* xp = x + (size_t)n * C_ * P_ + p;
    u32* op = g_x12 + (size_t)n * C_ * P_ + p;
    float ss = 0.0f;
#pragma unroll 8
    for (int c = 0; c < C_; c++) {
        float v = xp[(size_t)c * P_];
        ss = fmaf(v, v, ss);
        op[(size_t)c * P_] = split_pack_s(v);
    }
    g_invn[g] = 1.0f / fmaxf(sqrtf(ss), EPSF);

    if (blockIdx.x == 0) {
#pragma unroll
        for (int i = 0; i < 128; i++) {
            int idx = threadIdx.x + 256 * i;
            g_w12[idx] = split_pack_s(2.0f * ALPHAF * vocabs[idx]);
        }
        int lane = threadIdx.x & 31, w = threadIdx.x >> 5;
#pragma unroll
        for (int r = 0; r < 8; r++) {
            int k = w * 8 + r;
            float s = 0.0f;
#pragma unroll
            for (int j = 0; j < 16; j++) {
                float v = vocabs[k * C_ + lane + 32 * j];
                s = fmaf(v, v, s);
            }
#pragma unroll
            for (int o = 16; o; o >>= 1) s += __shfl_xor_sync(0xffffffffu, s, o);
            if (lane == 0) g_bias[k] = -ALPHAF * sqrtf(s);
        }
    } else if (blockIdx.x == 1) {
#pragma unroll
        for (int i = 0; i < 8; i++) g_asum[threadIdx.x + 256 * i] = 0.0f;
        if (threadIdx.x < N_) g_nss[threadIdx.x] = 0.0f;
    }
}

// ---------------------------------------------------------------------------
// K1: logits D[k=64, p=128] = sum_c (2a*w)[k,c] * x[c,p] via mma.sync fp16,
// scaled 2-plane split: d_hi += h*h; d_lo += h*m' + m'*h; D = d_hi + d_lo/2048.
// Softmax over k in registers. grid (8, 32), 128 thr.
// ---------------------------------------------------------------------------
__global__ __launch_bounds__(128) void k1_assign() {
    __shared__ __align__(16) char sm[24576];
    u32 sb = smem_u32(sm);
    const u32 WS = sb, XH = sb + 8192, XM = sb + 16384;

    int t = threadIdx.x;
    int warp = t >> 5, lane = t & 31;
    int g = lane >> 2, t4 = lane & 3;
    int jA = lane >> 3, rA = lane & 7;
    int n = blockIdx.y, p0 = blockIdx.x * 128;
    int pw = p0 + warp * 32;

    float dh[4][4][4], dl[4][4][4];
#pragma unroll
    for (int a = 0; a < 4; a++)
#pragma unroll
        for (int b = 0; b < 4; b++)
#pragma unroll
            for (int q = 0; q < 4; q++) { dh[a][b][q] = 0.0f; dl[a][b][q] = 0.0f; }

    const u32* xb = g_x12 + (size_t)n * C_ * P_ + p0;

    for (int ch = 0; ch < 16; ch++) {
        int c0 = ch * 32;
        __syncthreads();
        // stage w: 64k x 16 c-pairs (h blocks 0-3, m blocks 4-7)
#pragma unroll
        for (int i = 0; i < 8; i++) {
            int q = t + 128 * i;
            int k = q >> 4, cp = q & 15;
            uint2 e = *(const uint2*)(g_w12 + k * C_ + c0 + 2 * cp);
            u32 h = __byte_perm(e.x, e.y, 0x5410);
            u32 m = __byte_perm(e.x, e.y, 0x7632);
            int c = 2 * cp, cb = c >> 3;
            u32 row = k * 128 + (c & 7) * 2;
            *(u32*)(sm + row + (((u32)(cb)     ^ (k & 7)) << 4)) = h;
            *(u32*)(sm + row + (((u32)(cb + 4) ^ (k & 7)) << 4)) = m;
        }
        // stage x: 32c x 64 p-pairs, planes XH / XM
#pragma unroll
        for (int i = 0; i < 16; i++) {
            int q = t + 128 * i;
            int c = q >> 6, pp = q & 63;
            uint2 e = *(const uint2*)(xb + (size_t)(c0 + c) * P_ + 2 * pp);
            u32 h = __byte_perm(e.x, e.y, 0x5410);
            u32 m = __byte_perm(e.x, e.y, 0x7632);
            int p = 2 * pp, nb = p >> 3;
            u32 off = c * 256 + (((u32)nb ^ (c & 7)) << 4) + (p & 7) * 2;
            *(u32*)(sm + 8192 + off) = h;
            *(u32*)(sm + 16384 + off) = m;
        }
        __syncthreads();

#pragma unroll
        for (int ks = 0; ks < 2; ks++) {
            u32 Ah[4][4], Am[4][4], Bh[2][4], Bm[2][4];
#pragma unroll
            for (int mi = 0; mi < 4; mi++) {
                int k = mi * 16 + ((jA & 1) << 3) + rA;
                int cb = ks * 2 + (jA >> 1);
                ldsm4(Ah[mi], WS + k * 128 + (((u32)(cb)     ^ (k & 7)) << 4));
                ldsm4(Am[mi], WS + k * 128 + (((u32)(cb + 4) ^ (k & 7)) << 4));
            }
#pragma unroll
            for (int ni = 0; ni < 2; ni++) {
                int c = ks * 16 + ((jA & 1) << 3) + rA;
                int nb = warp * 4 + ni * 2 + (jA >> 1);
                u32 off = c * 256 + (((u32)nb ^ (c & 7)) << 4);
                ldsm4t(Bh[ni], XH + off);
                ldsm4t(Bm[ni], XM + off);
            }
#pragma unroll
            for (int mi = 0; mi < 4; mi++)
#pragma unroll
                for (int ni = 0; ni < 2; ni++)
#pragma unroll
                    for (int nh = 0; nh < 2; nh++) {
                        mma16816(dh[mi][ni * 2 + nh], Ah[mi], &Bh[ni][nh * 2]);
                        mma16816(dl[mi][ni * 2 + nh], Ah[mi], &Bm[ni][nh * 2]);
                        mma16816(dl[mi][ni * 2 + nh], Am[mi], &Bh[ni][nh * 2]);
                    }
        }
    }

    // combine planes: D = d_hi + d_lo / 2048
    float d[4][4][4];
#pragma unroll
    for (int mi = 0; mi < 4; mi++)
#pragma unroll
        for (int nj = 0; nj < 4; nj++)
#pragma unroll
            for (int q = 0; q < 4; q++)
                d[mi][nj][q] = fmaf(dl[mi][nj][q], INV_MSCALE, dh[mi][nj][q]);

    // ---------------- epilogue: bias + invn scale + softmax over k -----------
    float invp[4][2], bias[4][2];
#pragma unroll
    for (int nj = 0; nj < 4; nj++) {
        int p = pw + nj * 8 + 2 * t4;
        invp[nj][0] = g_invn[n * P_ + p];
        invp[nj][1] = g_invn[n * P_ + p + 1];
    }
#pragma unroll
    for (int mi = 0; mi < 4; mi++) {
        bias[mi][0] = g_bias[mi * 16 + g];
        bias[mi][1] = g_bias[mi * 16 + g + 8];
    }
    float lg[4][4][4];
    float mx[4][2];
#pragma unroll
    for (int nj = 0; nj < 4; nj++) { mx[nj][0] = -1e30f; mx[nj][1] = -1e30f; }
#pragma unroll
    for (int mi = 0; mi < 4; mi++)
#pragma unroll
        for (int nj = 0; nj < 4; nj++) {
            lg[mi][nj][0] = fmaf(d[mi][nj][0], invp[nj][0], bias[mi][0]);
            lg[mi][nj][1] = fmaf(d[mi][nj][1], invp[nj][1], bias[mi][0]);
            lg[mi][nj][2] = fmaf(d[mi][nj][2], invp[nj][0], bias[mi][1]);
            lg[mi][nj][3] = fmaf(d[mi][nj][3], invp[nj][1], bias[mi][1]);
            mx[nj][0] = fmaxf(mx[nj][0], fmaxf(lg[mi][nj][0], lg[mi][nj][2]));
            mx[nj][1] = fmaxf(mx[nj][1], fmaxf(lg[mi][nj][1], lg[mi][nj][3]));
        }
#pragma unroll
    for (int nj = 0; nj < 4; nj++)
#pragma unroll
        for (int cc = 0; cc < 2; cc++) {
            float m = mx[nj][cc];
#pragma unroll
            for (int o = 4; o <= 16; o <<= 1) m = fmaxf(m, __shfl_xor_sync(0xffffffffu, m, o));
            mx[nj][cc] = m;
        }
    float sm_[4][2];
#pragma unroll
    for (int nj = 0; nj < 4; nj++) { sm_[nj][0] = 0.0f; sm_[nj][1] = 0.0f; }
#pragma unroll
    for (int mi = 0; mi < 4; mi++)
#pragma unroll
        for (int nj = 0; nj < 4; nj++) {
            lg[mi][nj][0] = __expf(lg[mi][nj][0] - mx[nj][0]);
            lg[mi][nj][1] = __expf(lg[mi][nj][1] - mx[nj][1]);
            lg[mi][nj][2] = __expf(lg[mi][nj][2] - mx[nj][0]);
            lg[mi][nj][3] = __expf(lg[mi][nj][3] - mx[nj][1]);
            sm_[nj][0] += lg[mi][nj][0] + lg[mi][nj][2];
            sm_[nj][1] += lg[mi][nj][1] + lg[mi][nj][3];
        }
#pragma unroll
    for (int nj = 0; nj < 4; nj++)
#pragma unroll
        for (int cc = 0; cc < 2; cc++) {
            float s = sm_[nj][cc];
#pragma unroll
            for (int o = 4; o <= 16; o <<= 1) s += __shfl_xor_sync(0xffffffffu, s, o);
            sm_[nj][cc] = 1.0f / s;
        }
    // write atil = a*invp as bf16 (range covers tiny a) + asum partials
    float asl[4][2];
#pragma unroll
    for (int mi = 0; mi < 4; mi++) { asl[mi][0] = 0.0f; asl[mi][1] = 0.0f; }
    u16* ab = g_abf + (size_t)n * K_ * P_;
#pragma unroll
    for (int mi = 0; mi < 4; mi++)
#pragma unroll
        for (int nj = 0; nj < 4; nj++) {
            int p = pw + nj * 8 + 2 * t4;
            int k0_ = mi * 16 + g;
            float a00 = lg[mi][nj][0] * sm_[nj][0];
            float a01 = lg[mi][nj][1] * sm_[nj][1];
            float a10 = lg[mi][nj][2] * sm_[nj][0];
            float a11 = lg[mi][nj][3] * sm_[nj][1];
            asl[mi][0] += a00 + a01;
            asl[mi][1] += a10 + a11;
            u32 w0 = (u32)__bfloat16_as_ushort(__float2bfloat16(a00 * invp[nj][0])) |
                     ((u32)__bfloat16_as_ushort(__float2bfloat16(a01 * invp[nj][1])) << 16);
            u32 w1 = (u32)__bfloat16_as_ushort(__float2bfloat16(a10 * invp[nj][0])) |
                     ((u32)__bfloat16_as_ushort(__float2bfloat16(a11 * invp[nj][1])) << 16);
            *(u32*)(ab + (size_t)k0_ * P_ + p) = w0;
            *(u32*)(ab + (size_t)(k0_ + 8) * P_ + p) = w1;
        }
#pragma unroll
    for (int mi = 0; mi < 4; mi++)
#pragma unroll
        for (int h = 0; h < 2; h++) {
            float s = asl[mi][h];
            s += __shfl_xor_sync(0xffffffffu, s, 1);
            s += __shfl_xor_sync(0xffffffffu, s, 2);
            if (t4 == 0) atomicAdd(&g_asum[n * K_ + mi * 16 + g + 8 * h], s);
        }
}

// ---------------------------------------------------------------------------
// K2: vlad D[k=64, c=128] = sum_p atil[k,p] * x[c,p] via bf16 mma (single
// product; bf16 range avoids underflow, asum*vocab dominates precision).
// grid (4, 32), 128 thr.
// ---------------------------------------------------------------------------
__global__ __launch_bounds__(128) void k2_vlad(const float* __restrict__ vocabs,
                                               float* __restrict__ out) {
    __shared__ __align__(16) char sm[24576];
    u32 sb = smem_u32(sm);
    const u32 AS = sb, XS = sb + 8192;

    int t = threadIdx.x;
    int warp = t >> 5, lane = t & 31;
    int g = lane >> 2, t4 = lane & 3;
    int jA = lane >> 3, rA = lane & 7;
    int n = blockIdx.y, c0 = blockIdx.x * 128;

    float d[4][4][4];
#pragma unroll
    for (int a = 0; a < 4; a++)
#pragma unroll
        for (int b = 0; b < 4; b++)
#pragma unroll
            for (int q = 0; q < 4; q++) d[a][b][q] = 0.0f;

    const u16* ab = g_abf + (size_t)n * K_ * P_;
    const u32* xb = g_x12 + (size_t)n * C_ * P_;

    for (int ch = 0; ch < 32; ch++) {
        int p0 = ch * 32;
        __syncthreads();
        // stage atil (bf16): 64k x 16 p-pairs
#pragma unroll
        for (int i = 0; i < 8; i++) {
            int q = t + 128 * i;
            int k = q >> 4, pp = q & 15;
            u32 e = *(const u32*)(ab + (size_t)k * P_ + p0 + 2 * pp);
            int p = 2 * pp, pb = p >> 3;
            u32 row = k * 128 + (p & 7) * 2;
            *(u32*)(sm + row + (((u32)pb ^ (k & 7)) << 4)) = e;
        }
        // stage x (h plane -> bf16): 128c x 16 p-pairs
#pragma unroll
        for (int i = 0; i < 16; i++) {
            int q = t + 128 * i;
            int cr = q >> 4, pp = q & 15;
            uint2 e = *(const uint2*)(xb + (size_t)(c0 + cr) * P_ + p0 + 2 * pp);
            u32 val = (u32)h2bf((u16)(e.x & 0xffffu)) |
                      ((u32)h2bf((u16)(e.y & 0xffffu)) << 16);
            int p = 2 * pp, pb = p >> 3;
            u32 row = 8192 + cr * 128 + (p & 7) * 2;
            *(u32*)(sm + row + (((u32)pb ^ (cr & 7)) << 4)) = val;
        }
        __syncthreads();

#pragma unroll
        for (int ks = 0; ks < 2; ks++) {
            u32 Ah[4][4], Bh[2][4];
#pragma unroll
            for (int mi = 0; mi < 4; mi++) {
                int k = mi * 16 + ((jA & 1) << 3) + rA;
                int pb = ks * 2 + (jA >> 1);
                ldsm4(Ah[mi], AS + k * 128 + (((u32)pb ^ (k & 7)) << 4));
            }
#pragma unroll
            for (int ni = 0; ni < 2; ni++) {
                int cr = warp * 32 + ni * 16 + ((jA >> 1) << 3) + rA;
                int pb = ks * 2 + (jA & 1);
                ldsm4(Bh[ni], XS + cr * 128 + (((u32)pb ^ (cr & 7)) << 4));
            }
#pragma unroll
            for (int mi = 0; mi < 4; mi++)
#pragma unroll
                for (int ni = 0; ni < 2; ni++)
#pragma unroll
                    for (int nh = 0; nh < 2; nh++)
                        mma16816bf(d[mi][ni * 2 + nh], Ah[mi], &Bh[ni][nh * 2]);
        }
    }

    // epilogue: out[k][c] = d - asum[k]*vocab[k][c]
#pragma unroll
    for (int mi = 0; mi < 4; mi++) {
        int k0_ = mi * 16 + g;
        float s0 = g_asum[n * K_ + k0_];
        float s1 = g_asum[n * K_ + k0_ + 8];
#pragma unroll
        for (int nj = 0; nj < 4; nj++) {
            int c = c0 + warp * 32 + nj * 8 + 2 * t4;
            float2 v0 = *(const float2*)(vocabs + k0_ * C_ + c);
            float2 v1 = *(const float2*)(vocabs + (k0_ + 8) * C_ + c);
            float2 o0, o1;
            o0.x = fmaf(-s0, v0.x, d[mi][nj][0]);
            o0.y = fmaf(-s0, v0.y, d[mi][nj][1]);
            o1.x = fmaf(-s1, v1.x, d[mi][nj][2]);
            o1.y = fmaf(-s1, v1.y, d[mi][nj][3]);
            *(float2*)(out + ((size_t)n * K_ + k0_) * C_ + c) = o0;
            *(float2*)(out + ((size_t)n * K_ + k0_ + 8) * C_ + c) = o1;
        }
    }
}

// ---------------------------------------------------------------------------
__global__ __launch_bounds__(256) void k3a_intra(float* __restrict__ out) {
    int n = blockIdx.y, k = blockIdx.x, t = threadIdx.x;
    float* row = out + (size_t)n * (K_ * C_) + (size_t)k * C_;
    float2 v = *(float2*)(row + t * 2);
    float ss = v.x * v.x + v.y * v.y;
#pragma unroll
    for (int o = 16; o; o >>= 1) ss += __shfl_xor_sync(0xffffffffu, ss, o);
    __shared__ float wsum[8];
    if ((t & 31) == 0) wsum[t >> 5] = ss;
    __syncthreads();
    float tot = wsum[0] + wsum[1] + wsum[2] + wsum[3] + wsum[4] + wsum[5] + wsum[6] + wsum[7];
    float rinv = 1.0f / fmaxf(sqrtf(tot), EPSF);
    v.x *= rinv; v.y *= rinv;
    *(float2*)(row + t * 2) = v;
    if (t == 0) atomicAdd(&g_nss[n], tot * rinv * rinv);
}

__global__ __launch_bounds__(256) void k3b_final(float* __restrict__ out) {
    int g4 = blockIdx.x * 256 + threadIdx.x;
    int n = (g4 * 4) >> 15;
    float r = 1.0f / fmaxf(sqrtf(g_nss[n]), EPSF);
    float4 v = ((float4*)out)[g4];
    v.x *= r; v.y *= r; v.z *= r; v.w *= r;
    ((float4*)out)[g4] = v;
}

// ---------------------------------------------------------------------------
extern "C" void kernel_launch(void* const* d_in, const int* in_sizes, int n_in,
                              void* d_out, int out_size) {
    const float* x = (const float*)d_in[0];
    const float* vocabs = (const float*)d_in[1];
    if (n_in >= 2 && in_sizes[0] == K_ * C_ && in_sizes[1] == N_ * C_ * P_) {
        vocabs = (const float*)d_in[0];
        x = (const float*)d_in[1];
    }
    float* out = (float*)d_out;

    k0_prep<<<128, 256>>>(x, vocabs);
    k1_assign<<<dim3(8, 32), 128>>>();
    k2_vlad<<<dim3(4, 32), 128>>>(vocabs, out);
    k3a_intra<<<dim3(64, 32), 256>>>(out);
    k3b_final<<<1024, 256>>>(out);
}

// round 8
// speedup vs baseline: 1.4942x; 1.0640x over previous
#include <cuda_runtime.h>
#include <cuda_fp16.h>
#include <cuda_bf16.h>
#include <math.h>

#define N_ 32
#define C_ 512
#define P_ 1024
#define K_ 64
#define ALPHAF 100.0f
#define EPSF 1e-12f
#define MSCALE 2048.0f
#define INV_MSCALE 4.8828125e-4f

typedef unsigned int u32;
typedef unsigned short u16;

// ---------------- scratch ---------------------------------------------------
__device__ float g_invn[N_ * P_];
__device__ float g_bias[K_];
__device__ float g_asum[N_ * K_];
__device__ float g_rss[N_ * K_];              // row sum-squares of unnorm vlad
__device__ float g_scale[N_ * K_];            // final per-row scale
__device__ float g_ss4[4 * N_ * P_];          // partial c-sums for invn
__device__ u16 g_xh[(size_t)N_ * C_ * P_];    // fp16 h plane of x
__device__ u16 g_xm[(size_t)N_ * C_ * P_];    // fp16 (x-h)*2048 plane
__device__ u16 g_wh[K_ * C_];                 // fp16 h of 2*alpha*vocab
__device__ u16 g_wm[K_ * C_];                 // fp16 m of 2*alpha*vocab
__device__ u16 g_abf[(size_t)N_ * K_ * P_];   // bf16 of a*invn

// ---------------- helpers ----------------------------------------------------
__device__ __forceinline__ u32 smem_u32(const void* p) {
    u32 a;
    asm("{ .reg .u64 t; cvta.to.shared.u64 t, %1; cvt.u32.u64 %0, t; }" : "=r"(a) : "l"(p));
    return a;
}
__device__ __forceinline__ void ldsm4(u32* r, u32 addr) {
    asm volatile("ldmatrix.sync.aligned.m8n8.x4.shared.b16 {%0,%1,%2,%3}, [%4];"
                 : "=r"(r[0]), "=r"(r[1]), "=r"(r[2]), "=r"(r[3]) : "r"(addr));
}
__device__ __forceinline__ void ldsm4t(u32* r, u32 addr) {
    asm volatile("ldmatrix.sync.aligned.m8n8.x4.trans.shared.b16 {%0,%1,%2,%3}, [%4];"
                 : "=r"(r[0]), "=r"(r[1]), "=r"(r[2]), "=r"(r[3]) : "r"(addr));
}
__device__ __forceinline__ void mma16816(float* d, const u32* a, const u32* b) {
    asm volatile(
        "mma.sync.aligned.m16n8k16.row.col.f32.f16.f16.f32 "
        "{%0,%1,%2,%3}, {%4,%5,%6,%7}, {%8,%9}, {%0,%1,%2,%3};"
        : "+f"(d[0]), "+f"(d[1]), "+f"(d[2]), "+f"(d[3])
        : "r"(a[0]), "r"(a[1]), "r"(a[2]), "r"(a[3]), "r"(b[0]), "r"(b[1]));
}
__device__ __forceinline__ void mma16816bf(float* d, const u32* a, const u32* b) {
    asm volatile(
        "mma.sync.aligned.m16n8k16.row.col.f32.bf16.bf16.f32 "
        "{%0,%1,%2,%3}, {%4,%5,%6,%7}, {%8,%9}, {%0,%1,%2,%3};"
        : "+f"(d[0]), "+f"(d[1]), "+f"(d[2]), "+f"(d[3])
        : "r"(a[0]), "r"(a[1]), "r"(a[2]), "r"(a[3]), "r"(b[0]), "r"(b[1]));
}

// ---------------------------------------------------------------------------
// K0a: 4-way c-split: each thread covers 128 c's of one (n,p) column; writes
// x planes + partial sumsq (no atomics). grid 512 x 256.
// ---------------------------------------------------------------------------
__global__ __launch_bounds__(256) void k0a_split(const float* __restrict__ x) {
    int gg = blockIdx.x * 256 + threadIdx.x;     // 131072 = 4 * N * P
    int seg = gg >> 15;                          // 0..3
    int np = gg & 32767;                         // n*1024 + p
    int n = np >> 10, p = np & 1023;
    size_t base = (size_t)n * C_ * P_ + (size_t)(seg * 128) * P_ + p;
    const float* xp = x + base;
    u16* oh = g_xh + base;
    u16* om = g_xm + base;
    float ss = 0.0f;
#pragma unroll 8
    for (int c = 0; c < 128; c++) {
        float v = xp[(size_t)c * P_];
        ss = fmaf(v, v, ss);
        __half h = __float2half_rn(v);
        __half m = __float2half_rn((v - __half2float(h)) * MSCALE);
        oh[(size_t)c * P_] = __half_as_ushort(h);
        om[(size_t)c * P_] = __half_as_ushort(m);
    }
    g_ss4[seg * (N_ * P_) + np] = ss;
}

// ---------------------------------------------------------------------------
// K0b: combine partials -> invn. Block 0: w split + bias. Block 1: zero scratch.
// grid 128 x 256.
// ---------------------------------------------------------------------------
__global__ __launch_bounds__(256) void k0b_prep(const float* __restrict__ vocabs) {
    int g = blockIdx.x * 256 + threadIdx.x;      // 32768
    float ss = g_ss4[g] + g_ss4[N_ * P_ + g] + g_ss4[2 * N_ * P_ + g] + g_ss4[3 * N_ * P_ + g];
    g_invn[g] = 1.0f / fmaxf(sqrtf(ss), EPSF);

    if (blockIdx.x == 0) {
#pragma unroll
        for (int i = 0; i < 128; i++) {
            int idx = threadIdx.x + 256 * i;
            float v = 2.0f * ALPHAF * vocabs[idx];
            __half h = __float2half_rn(v);
            __half m = __float2half_rn((v - __half2float(h)) * MSCALE);
            g_wh[idx] = __half_as_ushort(h);
            g_wm[idx] = __half_as_ushort(m);
        }
        int lane = threadIdx.x & 31, w = threadIdx.x >> 5;
#pragma unroll
        for (int r = 0; r < 8; r++) {
            int k = w * 8 + r;
            float s = 0.0f;
#pragma unroll
            for (int j = 0; j < 16; j++) {
                float v = vocabs[k * C_ + lane + 32 * j];
                s = fmaf(v, v, s);
            }
#pragma unroll
            for (int o = 16; o; o >>= 1) s += __shfl_xor_sync(0xffffffffu, s, o);
            if (lane == 0) g_bias[k] = -ALPHAF * sqrtf(s);
        }
    } else if (blockIdx.x == 1) {
#pragma unroll
        for (int i = 0; i < 8; i++) {
            g_asum[threadIdx.x + 256 * i] = 0.0f;
            g_rss[threadIdx.x + 256 * i] = 0.0f;
        }
    }
}

// ---------------------------------------------------------------------------
// K1: logits D[k=64, p=128] = sum_c (2a*w)[k,c]*x[c,p], scaled 2-plane fp16,
// 64-c chunks (8 chunks). Softmax over k in regs. grid (8,32), 128 thr.
// smem 48KB: WH 8K | WM 8K | XH 16K | XM 16K.
// ---------------------------------------------------------------------------
__global__ __launch_bounds__(128) void k1_assign() {
    __shared__ __align__(16) char sm[49152];
    u32 sb = smem_u32(sm);
    const u32 WH = sb, WM = sb + 8192, XH = sb + 16384, XM = sb + 32768;

    int t = threadIdx.x;
    int warp = t >> 5, lane = t & 31;
    int g = lane >> 2, t4 = lane & 3;
    int jA = lane >> 3, rA = lane & 7;
    int n = blockIdx.y, p0 = blockIdx.x * 128;
    int pw = p0 + warp * 32;

    float dh[4][4][4], dl[4][4][4];
#pragma unroll
    for (int a = 0; a < 4; a++)
#pragma unroll
        for (int b = 0; b < 4; b++)
#pragma unroll
            for (int q = 0; q < 4; q++) { dh[a][b][q] = 0.0f; dl[a][b][q] = 0.0f; }

    const u16* xhb = g_xh + (size_t)n * C_ * P_ + p0;
    const u16* xmb = g_xm + (size_t)n * C_ * P_ + p0;

    for (int ch = 0; ch < 8; ch++) {
        int c0 = ch * 64;
        __syncthreads();
        // stage w: 64k x 32 c-pairs per plane
#pragma unroll
        for (int i = 0; i < 16; i++) {
            int q = t + 128 * i;
            int k = q >> 5, cp = q & 31;
            int c = 2 * cp, cb = c >> 3;
            u32 h = *(const u32*)(g_wh + k * C_ + c0 + c);
            u32 m = *(const u32*)(g_wm + k * C_ + c0 + c);
            u32 addr = (u32)(k * 128) + (((u32)cb ^ (u32)(k & 7)) << 4) + (c & 7) * 2;
            *(u32*)(sm + (WH - sb) + addr) = h;
            *(u32*)(sm + (WM - sb) + addr) = m;
        }
        // stage x: 64c x 64 p-pairs per plane
#pragma unroll
        for (int i = 0; i < 32; i++) {
            int q = t + 128 * i;
            int c = q >> 6, pp = q & 63;
            int p = 2 * pp, nb = p >> 3;
            size_t gix = (size_t)(c0 + c) * P_ + p;
            u32 h = *(const u32*)(xhb + gix);
            u32 m = *(const u32*)(xmb + gix);
            u32 off = (u32)(c * 256) + (((u32)nb ^ (u32)(c & 7)) << 4) + (p & 7) * 2;
            *(u32*)(sm + 16384 + off) = h;
            *(u32*)(sm + 32768 + off) = m;
        }
        __syncthreads();

#pragma unroll
        for (int ks = 0; ks < 4; ks++) {
            u32 Ah[4][4], Am[4][4], Bh[2][4], Bm[2][4];
#pragma unroll
            for (int mi = 0; mi < 4; mi++) {
                int k = mi * 16 + ((jA & 1) << 3) + rA;
                int cb = ks * 2 + (jA >> 1);
                u32 addr = (u32)(k * 128) + (((u32)cb ^ (u32)(k & 7)) << 4);
                ldsm4(Ah[mi], WH + addr);
                ldsm4(Am[mi], WM + addr);
            }
#pragma unroll
            for (int ni = 0; ni < 2; ni++) {
                int c = ks * 16 + ((jA & 1) << 3) + rA;
                int nb = warp * 4 + ni * 2 + (jA >> 1);
                u32 off = (u32)(c * 256) + (((u32)nb ^ (u32)(c & 7)) << 4);
                ldsm4t(Bh[ni], XH + off);
                ldsm4t(Bm[ni], XM + off);
            }
#pragma unroll
            for (int mi = 0; mi < 4; mi++)
#pragma unroll
                for (int ni = 0; ni < 2; ni++)
#pragma unroll
                    for (int nh = 0; nh < 2; nh++) {
                        mma16816(dh[mi][ni * 2 + nh], Ah[mi], &Bh[ni][nh * 2]);
                        mma16816(dl[mi][ni * 2 + nh], Ah[mi], &Bm[ni][nh * 2]);
                        mma16816(dl[mi][ni * 2 + nh], Am[mi], &Bh[ni][nh * 2]);
                    }
        }
    }

    // combine planes: D = d_hi + d_lo / 2048
    float d[4][4][4];
#pragma unroll
    for (int mi = 0; mi < 4; mi++)
#pragma unroll
        for (int nj = 0; nj < 4; nj++)
#pragma unroll
            for (int q = 0; q < 4; q++)
                d[mi][nj][q] = fmaf(dl[mi][nj][q], INV_MSCALE, dh[mi][nj][q]);

    // ---------------- epilogue: bias + invn + softmax over k -----------------
    float invp[4][2], bias[4][2];
#pragma unroll
    for (int nj = 0; nj < 4; nj++) {
        int p = pw + nj * 8 + 2 * t4;
        invp[nj][0] = g_invn[n * P_ + p];
        invp[nj][1] = g_invn[n * P_ + p + 1];
    }
#pragma unroll
    for (int mi = 0; mi < 4; mi++) {
        bias[mi][0] = g_bias[mi * 16 + g];
        bias[mi][1] = g_bias[mi * 16 + g + 8];
    }
    float lg[4][4][4];
    float mx[4][2];
#pragma unroll
    for (int nj = 0; nj < 4; nj++) { mx[nj][0] = -1e30f; mx[nj][1] = -1e30f; }
#pragma unroll
    for (int mi = 0; mi < 4; mi++)
#pragma unroll
        for (int nj = 0; nj < 4; nj++) {
            lg[mi][nj][0] = fmaf(d[mi][nj][0], invp[nj][0], bias[mi][0]);
            lg[mi][nj][1] = fmaf(d[mi][nj][1], invp[nj][1], bias[mi][0]);
            lg[mi][nj][2] = fmaf(d[mi][nj][2], invp[nj][0], bias[mi][1]);
            lg[mi][nj][3] = fmaf(d[mi][nj][3], invp[nj][1], bias[mi][1]);
            mx[nj][0] = fmaxf(mx[nj][0], fmaxf(lg[mi][nj][0], lg[mi][nj][2]));
            mx[nj][1] = fmaxf(mx[nj][1], fmaxf(lg[mi][nj][1], lg[mi][nj][3]));
        }
#pragma unroll
    for (int nj = 0; nj < 4; nj++)
#pragma unroll
        for (int cc = 0; cc < 2; cc++) {
            float m = mx[nj][cc];
#pragma unroll
            for (int o = 4; o <= 16; o <<= 1) m = fmaxf(m, __shfl_xor_sync(0xffffffffu, m, o));
            mx[nj][cc] = m;
        }
    float sx[4][2];
#pragma unroll
    for (int nj = 0; nj < 4; nj++) { sx[nj][0] = 0.0f; sx[nj][1] = 0.0f; }
#pragma unroll
    for (int mi = 0; mi < 4; mi++)
#pragma unroll
        for (int nj = 0; nj < 4; nj++) {
            lg[mi][nj][0] = __expf(lg[mi][nj][0] - mx[nj][0]);
            lg[mi][nj][1] = __expf(lg[mi][nj][1] - mx[nj][1]);
            lg[mi][nj][2] = __expf(lg[mi][nj][2] - mx[nj][0]);
            lg[mi][nj][3] = __expf(lg[mi][nj][3] - mx[nj][1]);
            sx[nj][0] += lg[mi][nj][0] + lg[mi][nj][2];
            sx[nj][1] += lg[mi][nj][1] + lg[mi][nj][3];
        }
#pragma unroll
    for (int nj = 0; nj < 4; nj++)
#pragma unroll
        for (int cc = 0; cc < 2; cc++) {
            float s = sx[nj][cc];
#pragma unroll
            for (int o = 4; o <= 16; o <<= 1) s += __shfl_xor_sync(0xffffffffu, s, o);
            sx[nj][cc] = 1.0f / s;
        }
    float asl[4][2];
#pragma unroll
    for (int mi = 0; mi < 4; mi++) { asl[mi][0] = 0.0f; asl[mi][1] = 0.0f; }
    u16* ab = g_abf + (size_t)n * K_ * P_;
#pragma unroll
    for (int mi = 0; mi < 4; mi++)
#pragma unroll
        for (int nj = 0; nj < 4; nj++) {
            int p = pw + nj * 8 + 2 * t4;
            int k0_ = mi * 16 + g;
            float a00 = lg[mi][nj][0] * sx[nj][0];
            float a01 = lg[mi][nj][1] * sx[nj][1];
            float a10 = lg[mi][nj][2] * sx[nj][0];
            float a11 = lg[mi][nj][3] * sx[nj][1];
            asl[mi][0] += a00 + a01;
            asl[mi][1] += a10 + a11;
            u32 w0 = (u32)__bfloat16_as_ushort(__float2bfloat16(a00 * invp[nj][0])) |
                     ((u32)__bfloat16_as_ushort(__float2bfloat16(a01 * invp[nj][1])) << 16);
            u32 w1 = (u32)__bfloat16_as_ushort(__float2bfloat16(a10 * invp[nj][0])) |
                     ((u32)__bfloat16_as_ushort(__float2bfloat16(a11 * invp[nj][1])) << 16);
            *(u32*)(ab + (size_t)k0_ * P_ + p) = w0;
            *(u32*)(ab + (size_t)(k0_ + 8) * P_ + p) = w1;
        }
#pragma unroll
    for (int mi = 0; mi < 4; mi++)
#pragma unroll
        for (int h = 0; h < 2; h++) {
            float s = asl[mi][h];
            s += __shfl_xor_sync(0xffffffffu, s, 1);
            s += __shfl_xor_sync(0xffffffffu, s, 2);
            if (t4 == 0) atomicAdd(&g_asum[n * K_ + mi * 16 + g + 8 * h], s);
        }
}

// ---------------------------------------------------------------------------
// K2: vlad D[k=64, c=128] = sum_p atil[k,p]*x[c,p] via bf16 mma, 64-p chunks
// (16 chunks). Epilogue subtracts asum*vocab, accumulates row sumsq atomics.
// grid (4,32), 128 thr. smem 24KB: AS 8K | XS 16K.
// ---------------------------------------------------------------------------
__global__ __launch_bounds__(128) void k2_vlad(const float* __restrict__ vocabs,
                                               float* __restrict__ out) {
    __shared__ __align__(16) char sm[24576];
    u32 sb = smem_u32(sm);
    const u32 AS = sb, XS = sb + 8192;

    int t = threadIdx.x;
    int warp = t >> 5, lane = t & 31;
    int g = lane >> 2, t4 = lane & 3;
    int jA = lane >> 3, rA = lane & 7;
    int n = blockIdx.y, c0 = blockIdx.x * 128;

    float d[4][4][4];
#pragma unroll
    for (int a = 0; a < 4; a++)
#pragma unroll
        for (int b = 0; b < 4; b++)
#pragma unroll
            for (int q = 0; q < 4; q++) d[a][b][q] = 0.0f;

    const u16* ab = g_abf + (size_t)n * K_ * P_;
    const u16* xb = g_xh + (size_t)n * C_ * P_;

    for (int ch = 0; ch < 16; ch++) {
        int p0 = ch * 64;
        __syncthreads();
        // stage atil (bf16): 64k x 32 p-pairs
#pragma unroll
        for (int i = 0; i < 16; i++) {
            int q = t + 128 * i;
            int k = q >> 5, pp = q & 31;
            int p = 2 * pp, pb = p >> 3;
            u32 e = *(const u32*)(ab + (size_t)k * P_ + p0 + p);
            u32 addr = (u32)(k * 128) + (((u32)pb ^ (u32)(k & 7)) << 4) + (p & 7) * 2;
            *(u32*)(sm + addr) = e;
        }
        // stage x (h plane fp16 -> bf16): 128c x 32 p-pairs
#pragma unroll
        for (int i = 0; i < 32; i++) {
            int q = t + 128 * i;
            int cr = q >> 5, pp = q & 31;
            int p = 2 * pp, pb = p >> 3;
            u32 e = *(const u32*)(xb + (size_t)(c0 + cr) * P_ + p0 + p);
            __half2 hv = *reinterpret_cast<__half2*>(&e);
            float2 f = __half22float2(hv);
            __nv_bfloat162 b2 = __float22bfloat162_rn(f);
            u32 val = *reinterpret_cast<u32*>(&b2);
            u32 addr = 8192u + (u32)(cr * 128) + (((u32)pb ^ (u32)(cr & 7)) << 4) + (p & 7) * 2;
            *(u32*)(sm + addr) = val;
        }
        __syncthreads();

#pragma unroll
        for (int ks = 0; ks < 4; ks++) {
            u32 Ah[4][4], Bh[2][4];
#pragma unroll
            for (int mi = 0; mi < 4; mi++) {
                int k = mi * 16 + ((jA & 1) << 3) + rA;
                int pb = ks * 2 + (jA >> 1);
                ldsm4(Ah[mi], AS + k * 128 + (((u32)pb ^ (u32)(k & 7)) << 4));
            }
#pragma unroll
            for (int ni = 0; ni < 2; ni++) {
                int cr = warp * 32 + ni * 16 + ((jA >> 1) << 3) + rA;
                int pb = ks * 2 + (jA & 1);
                ldsm4(Bh[ni], XS + cr * 128 + (((u32)pb ^ (u32)(cr & 7)) << 4));
            }
#pragma unroll
            for (int mi = 0; mi < 4; mi++)
#pragma unroll
                for (int ni = 0; ni < 2; ni++)
#pragma unroll
                    for (int nh = 0; nh < 2; nh++)
                        mma16816bf(d[mi][ni * 2 + nh], Ah[mi], &Bh[ni][nh * 2]);
        }
    }

    // epilogue: out = d - asum*vocab; accumulate row sumsq
#pragma unroll
    for (int mi = 0; mi < 4; mi++) {
        int k0_ = mi * 16 + g;
        float s0 = g_asum[n * K_ + k0_];
        float s1 = g_asum[n * K_ + k0_ + 8];
        float r0 = 0.0f, r1 = 0.0f;
#pragma unroll
        for (int nj = 0; nj < 4; nj++) {
            int c = c0 + warp * 32 + nj * 8 + 2 * t4;
            float2 v0 = *(const float2*)(vocabs + k0_ * C_ + c);
            float2 v1 = *(const float2*)(vocabs + (k0_ + 8) * C_ + c);
            float2 o0, o1;
            o0.x = fmaf(-s0, v0.x, d[mi][nj][0]);
            o0.y = fmaf(-s0, v0.y, d[mi][nj][1]);
            o1.x = fmaf(-s1, v1.x, d[mi][nj][2]);
            o1.y = fmaf(-s1, v1.y, d[mi][nj][3]);
            r0 += o0.x * o0.x + o0.y * o0.y;
            r1 += o1.x * o1.x + o1.y * o1.y;
            *(float2*)(out + ((size_t)n * K_ + k0_) * C_ + c) = o0;
            *(float2*)(out + ((size_t)n * K_ + k0_ + 8) * C_ + c) = o1;
        }
        r0 += __shfl_xor_sync(0xffffffffu, r0, 1);
        r0 += __shfl_xor_sync(0xffffffffu, r0, 2);
        r1 += __shfl_xor_sync(0xffffffffu, r1, 1);
        r1 += __shfl_xor_sync(0xffffffffu, r1, 2);
        if (t4 == 0) {
            atomicAdd(&g_rss[n * K_ + k0_], r0);
            atomicAdd(&g_rss[n * K_ + k0_ + 8], r1);
        }
    }
}

// ---------------------------------------------------------------------------
// K2b: per-row final scale = rinv_row * 1/max(sqrt(nss),eps). grid 32 x 64.
// ---------------------------------------------------------------------------
__global__ __launch_bounds__(64) void k2b_scale() {
    int n = blockIdx.x, k = threadIdx.x;
    float tot = g_rss[n * K_ + k];
    float rinv = 1.0f / fmaxf(sqrtf(tot), EPSF);
    float contrib = tot * rinv * rinv;
    // reduce contrib over 64 threads (2 warps)
    float s = contrib;
#pragma unroll
    for (int o = 16; o; o >>= 1) s += __shfl_xor_sync(0xffffffffu, s, o);
    __shared__ float w2[2];
    if ((k & 31) == 0) w2[k >> 5] = s;
    __syncthreads();
    float nss = w2[0] + w2[1];
    g_scale[n * K_ + k] = rinv / fmaxf(sqrtf(nss), EPSF);
}

// ---------------------------------------------------------------------------
// K3: single streaming normalization pass. grid (64, 32), 128 thr, float4.
// ---------------------------------------------------------------------------
__global__ __launch_bounds__(128) void k3_norm(float* __restrict__ out) {
    int n = blockIdx.y, k = blockIdx.x, t = threadIdx.x;
    float sc = g_scale[n * K_ + k];
    float4* row = (float4*)(out + (size_t)n * (K_ * C_) + (size_t)k * C_);
    float4 v = row[t];
    v.x *= sc; v.y *= sc; v.z *= sc; v.w *= sc;
    row[t] = v;
}

// ---------------------------------------------------------------------------
extern "C" void kernel_launch(void* const* d_in, const int* in_sizes, int n_in,
                              void* d_out, int out_size) {
    const float* x = (const float*)d_in[0];
    const float* vocabs = (const float*)d_in[1];
    if (n_in >= 2 && in_sizes[0] == K_ * C_ && in_sizes[1] == N_ * C_ * P_) {
        vocabs = (const float*)d_in[0];
        x = (const float*)d_in[1];
    }
    float* out = (float*)d_out;

    k0a_split<<<512, 256>>>(x);
    k0b_prep<<<128, 256>>>(vocabs);
    k1_assign<<<dim3(8, 32), 128>>>();
    k2_vlad<<<dim3(4, 32), 128>>>(vocabs, out);
    k2b_scale<<<32, 64>>>();
    k3_norm<<<dim3(64, 32), 128>>>(out);
}

// round 9
// speedup vs baseline: 3.6644x; 2.4524x over previous
#include <cuda_runtime.h>
#include <cuda_fp16.h>
#include <cuda_bf16.h>
#include <math.h>

#define N_ 32
#define C_ 512
#define P_ 1024
#define K_ 64
#define ALPHAF 100.0f
#define EPSF 1e-12f
#define MSCALE 2048.0f
#define INV_MSCALE 4.8828125e-4f

typedef unsigned int u32;
typedef unsigned short u16;

// ---------------- scratch ---------------------------------------------------
__device__ float g_bias[K_];
__device__ float g_asum[N_ * K_];
__device__ float g_rss[N_ * K_];
__device__ float g_scale[N_ * K_];
__device__ u16 g_abf[(size_t)N_ * K_ * P_];   // bf16 of a*invn

// ---------------- helpers ----------------------------------------------------
__device__ __forceinline__ u32 smem_u32(const void* p) {
    u32 a;
    asm("{ .reg .u64 t; cvta.to.shared.u64 t, %1; cvt.u32.u64 %0, t; }" : "=r"(a) : "l"(p));
    return a;
}
__device__ __forceinline__ void ldsm4(u32* r, u32 addr) {
    asm volatile("ldmatrix.sync.aligned.m8n8.x4.shared.b16 {%0,%1,%2,%3}, [%4];"
                 : "=r"(r[0]), "=r"(r[1]), "=r"(r[2]), "=r"(r[3]) : "r"(addr));
}
__device__ __forceinline__ void ldsm4t(u32* r, u32 addr) {
    asm volatile("ldmatrix.sync.aligned.m8n8.x4.trans.shared.b16 {%0,%1,%2,%3}, [%4];"
                 : "=r"(r[0]), "=r"(r[1]), "=r"(r[2]), "=r"(r[3]) : "r"(addr));
}
__device__ __forceinline__ void mma16816(float* d, const u32* a, const u32* b) {
    asm volatile(
        "mma.sync.aligned.m16n8k16.row.col.f32.f16.f16.f32 "
        "{%0,%1,%2,%3}, {%4,%5,%6,%7}, {%8,%9}, {%0,%1,%2,%3};"
        : "+f"(d[0]), "+f"(d[1]), "+f"(d[2]), "+f"(d[3])
        : "r"(a[0]), "r"(a[1]), "r"(a[2]), "r"(a[3]), "r"(b[0]), "r"(b[1]));
}
__device__ __forceinline__ void mma16816bf(float* d, const u32* a, const u32* b) {
    asm volatile(
        "mma.sync.aligned.m16n8k16.row.col.f32.bf16.bf16.f32 "
        "{%0,%1,%2,%3}, {%4,%5,%6,%7}, {%8,%9}, {%0,%1,%2,%3};"
        : "+f"(d[0]), "+f"(d[1]), "+f"(d[2]), "+f"(d[3])
        : "r"(a[0]), "r"(a[1]), "r"(a[2]), "r"(a[3]), "r"(b[0]), "r"(b[1]));
}
__device__ __forceinline__ void split2(float v, u32& hbits, u32& mbits) {
    __half h = __float2half_rn(v);
    __half m = __float2half_rn((v - __half2float(h)) * MSCALE);
    hbits = (u32)__half_as_ushort(h);
    mbits = (u32)__half_as_ushort(m);
}

// ---------------------------------------------------------------------------
// K_init: block 0 computes bias; block 1 zeros asum/rss. grid 2 x 256.
// ---------------------------------------------------------------------------
__global__ __launch_bounds__(256) void k_init(const float* __restrict__ vocabs) {
    if (blockIdx.x == 0) {
        int lane = threadIdx.x & 31, w = threadIdx.x >> 5;
#pragma unroll
        for (int r = 0; r < 8; r++) {
            int k = w * 8 + r;
            float s = 0.0f;
#pragma unroll
            for (int j = 0; j < 16; j++) {
                float v = vocabs[k * C_ + lane + 32 * j];
                s = fmaf(v, v, s);
            }
#pragma unroll
            for (int o = 16; o; o >>= 1) s += __shfl_xor_sync(0xffffffffu, s, o);
            if (lane == 0) g_bias[k] = -ALPHAF * sqrtf(s);
        }
    } else {
#pragma unroll
        for (int i = 0; i < 8; i++) {
            g_asum[threadIdx.x + 256 * i] = 0.0f;
            g_rss[threadIdx.x + 256 * i] = 0.0f;
        }
    }
}

// ---------------------------------------------------------------------------
// K1: logits D[k=64, p=128] = sum_c (2a*w)[k,c]*x[c,p]. On-the-fly fp16
// 2-plane split from fp32 x/vocabs; per-p sumsq accumulated for invn.
// grid (8,32), 128 thr. smem 48KB: WH 8K | WM 8K | XH 16K | XM 16K.
// ---------------------------------------------------------------------------
__global__ __launch_bounds__(128) void k1_assign(const float* __restrict__ x,
                                                 const float* __restrict__ vocabs) {
    __shared__ __align__(16) char sm[49152];
    u32 sb = smem_u32(sm);
    const u32 WH = sb, WM = sb + 8192, XH = sb + 16384, XM = sb + 32768;
    float* ssacc = (float*)sm;   // aliases WH region AFTER mainloop

    int t = threadIdx.x;
    int warp = t >> 5, lane = t & 31;
    int g = lane >> 2, t4 = lane & 3;
    int jA = lane >> 3, rA = lane & 7;
    int n = blockIdx.y, p0 = blockIdx.x * 128;
    int pw = warp * 32;             // local p base of this warp

    float dh[4][4][4], dl[4][4][4];
#pragma unroll
    for (int a = 0; a < 4; a++)
#pragma unroll
        for (int b = 0; b < 4; b++)
#pragma unroll
            for (int q = 0; q < 4; q++) { dh[a][b][q] = 0.0f; dl[a][b][q] = 0.0f; }

    const float* xb = x + (size_t)n * C_ * P_ + p0;
    int px = 2 * (t & 63);          // fixed p-pair this thread stages
    int cpar = t >> 6;              // c parity
    int nbx = px >> 3;
    float ssx = 0.0f, ssy = 0.0f;

    for (int ch = 0; ch < 8; ch++) {
        int c0 = ch * 64;
        __syncthreads();
        // stage w from fp32 vocabs (2*alpha), split h/m
        {
            int cp = t & 31;
            int c = 2 * cp, cb = c >> 3;
#pragma unroll
            for (int i = 0; i < 16; i++) {
                int k = (t >> 5) + 4 * i;
                float2 v = *(const float2*)(vocabs + k * C_ + c0 + c);
                v.x *= 2.0f * ALPHAF; v.y *= 2.0f * ALPHAF;
                u32 hx, mx_, hy, my_;
                split2(v.x, hx, mx_);
                split2(v.y, hy, my_);
                u32 hp = hx | (hy << 16), mp = mx_ | (my_ << 16);
                u32 addr = (u32)(k * 128) + (((u32)cb ^ (u32)(k & 7)) << 4) + (c & 7) * 2;
                *(u32*)(sm + (WH - sb) + addr) = hp;
                *(u32*)(sm + (WM - sb) + addr) = mp;
            }
        }
        // stage x from fp32, split h/m, accumulate sumsq for this p-pair
#pragma unroll
        for (int i = 0; i < 32; i++) {
            int cc = cpar + 2 * i;
            float2 v = *(const float2*)(xb + (size_t)(c0 + cc) * P_ + px);
            ssx = fmaf(v.x, v.x, ssx);
            ssy = fmaf(v.y, v.y, ssy);
            u32 hx, mx_, hy, my_;
            split2(v.x, hx, mx_);
            split2(v.y, hy, my_);
            u32 off = (u32)(cc * 256) + (((u32)nbx ^ (u32)(cc & 7)) << 4) + (px & 7) * 2;
            *(u32*)(sm + 16384 + off) = hx | (hy << 16);
            *(u32*)(sm + 32768 + off) = mx_ | (my_ << 16);
        }
        __syncthreads();

#pragma unroll
        for (int ks = 0; ks < 4; ks++) {
            u32 Ah[4][4], Am[4][4], Bh[2][4], Bm[2][4];
#pragma unroll
            for (int mi = 0; mi < 4; mi++) {
                int k = mi * 16 + ((jA & 1) << 3) + rA;
                int cb = ks * 2 + (jA >> 1);
                u32 addr = (u32)(k * 128) + (((u32)cb ^ (u32)(k & 7)) << 4);
                ldsm4(Ah[mi], WH + addr);
                ldsm4(Am[mi], WM + addr);
            }
#pragma unroll
            for (int ni = 0; ni < 2; ni++) {
                int c = ks * 16 + ((jA & 1) << 3) + rA;
                int nb = warp * 4 + ni * 2 + (jA >> 1);
                u32 off = (u32)(c * 256) + (((u32)nb ^ (u32)(c & 7)) << 4);
                ldsm4t(Bh[ni], XH + off);
                ldsm4t(Bm[ni], XM + off);
            }
#pragma unroll
            for (int mi = 0; mi < 4; mi++)
#pragma unroll
                for (int ni = 0; ni < 2; ni++)
#pragma unroll
                    for (int nh = 0; nh < 2; nh++) {
                        mma16816(dh[mi][ni * 2 + nh], Ah[mi], &Bh[ni][nh * 2]);
                        mma16816(dl[mi][ni * 2 + nh], Ah[mi], &Bm[ni][nh * 2]);
                        mma16816(dl[mi][ni * 2 + nh], Am[mi], &Bh[ni][nh * 2]);
                    }
        }
    }

    // per-p inverse norms into smem (reuse WH region)
    __syncthreads();
    ssacc[t] = 0.0f;
    __syncthreads();
    atomicAdd(&ssacc[px], ssx);
    atomicAdd(&ssacc[px + 1], ssy);
    __syncthreads();

    // combine planes: D = d_hi + d_lo / 2048
    float d[4][4][4];
#pragma unroll
    for (int mi = 0; mi < 4; mi++)
#pragma unroll
        for (int nj = 0; nj < 4; nj++)
#pragma unroll
            for (int q = 0; q < 4; q++)
                d[mi][nj][q] = fmaf(dl[mi][nj][q], INV_MSCALE, dh[mi][nj][q]);

    // epilogue: bias + invn + softmax over k
    float invp[4][2], bias[4][2];
#pragma unroll
    for (int nj = 0; nj < 4; nj++) {
        int pl = pw + nj * 8 + 2 * t4;
        invp[nj][0] = 1.0f / fmaxf(sqrtf(ssacc[pl]), EPSF);
        invp[nj][1] = 1.0f / fmaxf(sqrtf(ssacc[pl + 1]), EPSF);
    }
#pragma unroll
    for (int mi = 0; mi < 4; mi++) {
        bias[mi][0] = g_bias[mi * 16 + g];
        bias[mi][1] = g_bias[mi * 16 + g + 8];
    }
    float lg[4][4][4];
    float mx[4][2];
#pragma unroll
    for (int nj = 0; nj < 4; nj++) { mx[nj][0] = -1e30f; mx[nj][1] = -1e30f; }
#pragma unroll
    for (int mi = 0; mi < 4; mi++)
#pragma unroll
        for (int nj = 0; nj < 4; nj++) {
            lg[mi][nj][0] = fmaf(d[mi][nj][0], invp[nj][0], bias[mi][0]);
            lg[mi][nj][1] = fmaf(d[mi][nj][1], invp[nj][1], bias[mi][0]);
            lg[mi][nj][2] = fmaf(d[mi][nj][2], invp[nj][0], bias[mi][1]);
            lg[mi][nj][3] = fmaf(d[mi][nj][3], invp[nj][1], bias[mi][1]);
            mx[nj][0] = fmaxf(mx[nj][0], fmaxf(lg[mi][nj][0], lg[mi][nj][2]));
            mx[nj][1] = fmaxf(mx[nj][1], fmaxf(lg[mi][nj][1], lg[mi][nj][3]));
        }
#pragma unroll
    for (int nj = 0; nj < 4; nj++)
#pragma unroll
        for (int cc = 0; cc < 2; cc++) {
            float m = mx[nj][cc];
#pragma unroll
            for (int o = 4; o <= 16; o <<= 1) m = fmaxf(m, __shfl_xor_sync(0xffffffffu, m, o));
            mx[nj][cc] = m;
        }
    float sx[4][2];
#pragma unroll
    for (int nj = 0; nj < 4; nj++) { sx[nj][0] = 0.0f; sx[nj][1] = 0.0f; }
#pragma unroll
    for (int mi = 0; mi < 4; mi++)
#pragma unroll
        for (int nj = 0; nj < 4; nj++) {
            lg[mi][nj][0] = __expf(lg[mi][nj][0] - mx[nj][0]);
            lg[mi][nj][1] = __expf(lg[mi][nj][1] - mx[nj][1]);
            lg[mi][nj][2] = __expf(lg[mi][nj][2] - mx[nj][0]);
            lg[mi][nj][3] = __expf(lg[mi][nj][3] - mx[nj][1]);
            sx[nj][0] += lg[mi][nj][0] + lg[mi][nj][2];
            sx[nj][1] += lg[mi][nj][1] + lg[mi][nj][3];
        }
#pragma unroll
    for (int nj = 0; nj < 4; nj++)
#pragma unroll
        for (int cc = 0; cc < 2; cc++) {
            float s = sx[nj][cc];
#pragma unroll
            for (int o = 4; o <= 16; o <<= 1) s += __shfl_xor_sync(0xffffffffu, s, o);
            sx[nj][cc] = 1.0f / s;
        }
    float asl[4][2];
#pragma unroll
    for (int mi = 0; mi < 4; mi++) { asl[mi][0] = 0.0f; asl[mi][1] = 0.0f; }
    u16* ab = g_abf + (size_t)n * K_ * P_;
#pragma unroll
    for (int mi = 0; mi < 4; mi++)
#pragma unroll
        for (int nj = 0; nj < 4; nj++) {
            int p = p0 + pw + nj * 8 + 2 * t4;
            int k0_ = mi * 16 + g;
            float a00 = lg[mi][nj][0] * sx[nj][0];
            float a01 = lg[mi][nj][1] * sx[nj][1];
            float a10 = lg[mi][nj][2] * sx[nj][0];
            float a11 = lg[mi][nj][3] * sx[nj][1];
            asl[mi][0] += a00 + a01;
            asl[mi][1] += a10 + a11;
            u32 w0 = (u32)__bfloat16_as_ushort(__float2bfloat16(a00 * invp[nj][0])) |
                     ((u32)__bfloat16_as_ushort(__float2bfloat16(a01 * invp[nj][1])) << 16);
            u32 w1 = (u32)__bfloat16_as_ushort(__float2bfloat16(a10 * invp[nj][0])) |
                     ((u32)__bfloat16_as_ushort(__float2bfloat16(a11 * invp[nj][1])) << 16);
            *(u32*)(ab + (size_t)k0_ * P_ + p) = w0;
            *(u32*)(ab + (size_t)(k0_ + 8) * P_ + p) = w1;
        }
#pragma unroll
    for (int mi = 0; mi < 4; mi++)
#pragma unroll
        for (int h = 0; h < 2; h++) {
            float s = asl[mi][h];
            s += __shfl_xor_sync(0xffffffffu, s, 1);
            s += __shfl_xor_sync(0xffffffffu, s, 2);
            if (t4 == 0) atomicAdd(&g_asum[n * K_ + mi * 16 + g + 8 * h], s);
        }
}

// ---------------------------------------------------------------------------
// K2: vlad D[k=64, c=64] = sum_p atil[k,p]*x[c,p] via bf16 mma. x converted
// fp32->bf16 on the fly. grid (8,32) = 256 blocks (2 CTA/SM), 128 thr.
// p-chunks of 128 (8 chunks). smem 32KB: AS 16K | XS 16K (256B rows).
// ---------------------------------------------------------------------------
__global__ __launch_bounds__(128) void k2_vlad(const float* __restrict__ x,
                                               const float* __restrict__ vocabs,
                                               float* __restrict__ out) {
    __shared__ __align__(16) char sm[32768];
    u32 sb = smem_u32(sm);
    const u32 AS = sb, XS = sb + 16384;

    int t = threadIdx.x;
    int warp = t >> 5, lane = t & 31;
    int g = lane >> 2, t4 = lane & 3;
    int jA = lane >> 3, rA = lane & 7;
    int n = blockIdx.y, c0 = blockIdx.x * 64;

    float d[4][2][4];
#pragma unroll
    for (int a = 0; a < 4; a++)
#pragma unroll
        for (int b = 0; b < 2; b++)
#pragma unroll
            for (int q = 0; q < 4; q++) d[a][b][q] = 0.0f;

    const u16* ab = g_abf + (size_t)n * K_ * P_;
    const float* xb = x + (size_t)n * C_ * P_;

    for (int ch = 0; ch < 8; ch++) {
        int p0 = ch * 128;
        __syncthreads();
        // stage atil (bf16, direct): 64k x 64 p-pairs
#pragma unroll
        for (int i = 0; i < 32; i++) {
            int q = t + 128 * i;
            int k = q >> 6, pp = q & 63;
            int p = 2 * pp;
            u32 e = *(const u32*)(ab + (size_t)k * P_ + p0 + p);
            u32 addr = (u32)(k * 256) + ((((u32)(p >> 3)) ^ (u32)(k & 7)) << 4) + (p & 7) * 2;
            *(u32*)(sm + addr) = e;
        }
        // stage x (fp32 -> bf16): 64c x 64 p-pairs
#pragma unroll
        for (int i = 0; i < 32; i++) {
            int q = t + 128 * i;
            int cr = q >> 6, pp = q & 63;
            int p = 2 * pp;
            float2 v = *(const float2*)(xb + (size_t)(c0 + cr) * P_ + p0 + p);
            __nv_bfloat162 b2 = __float22bfloat162_rn(v);
            u32 val = *reinterpret_cast<u32*>(&b2);
            u32 addr = 16384u + (u32)(cr * 256) + ((((u32)(p >> 3)) ^ (u32)(cr & 7)) << 4) + (p & 7) * 2;
            *(u32*)(sm + addr) = val;
        }
        __syncthreads();

#pragma unroll
        for (int ks = 0; ks < 8; ks++) {
            u32 Ah[4][4], Bh[4];
#pragma unroll
            for (int mi = 0; mi < 4; mi++) {
                int k = mi * 16 + ((jA & 1) << 3) + rA;
                u32 pbv = (u32)(ks * 2 + (jA >> 1));
                ldsm4(Ah[mi], AS + k * 256 + ((pbv ^ (u32)(k & 7)) << 4));
            }
            {
                int cr = warp * 16 + ((jA >> 1) << 3) + rA;
                u32 pbv = (u32)(ks * 2 + (jA & 1));
                ldsm4(Bh, XS + cr * 256 + ((pbv ^ (u32)(cr & 7)) << 4));
            }
#pragma unroll
            for (int mi = 0; mi < 4; mi++)
#pragma unroll
                for (int nh = 0; nh < 2; nh++)
                    mma16816bf(d[mi][nh], Ah[mi], &Bh[nh * 2]);
        }
    }

    // epilogue: out = d - asum*vocab; accumulate row sumsq
#pragma unroll
    for (int mi = 0; mi < 4; mi++) {
        int k0_ = mi * 16 + g;
        float s0 = g_asum[n * K_ + k0_];
        float s1 = g_asum[n * K_ + k0_ + 8];
        float r0 = 0.0f, r1 = 0.0f;
#pragma unroll
        for (int nb = 0; nb < 2; nb++) {
            int c = c0 + warp * 16 + nb * 8 + 2 * t4;
            float2 v0 = *(const float2*)(vocabs + k0_ * C_ + c);
            float2 v1 = *(const float2*)(vocabs + (k0_ + 8) * C_ + c);
            float2 o0, o1;
            o0.x = fmaf(-s0, v0.x, d[mi][nb][0]);
            o0.y = fmaf(-s0, v0.y, d[mi][nb][1]);
            o1.x = fmaf(-s1, v1.x, d[mi][nb][2]);
            o1.y = fmaf(-s1, v1.y, d[mi][nb][3]);
            r0 += o0.x * o0.x + o0.y * o0.y;
            r1 += o1.x * o1.x + o1.y * o1.y;
            *(float2*)(out + ((size_t)n * K_ + k0_) * C_ + c) = o0;
            *(float2*)(out + ((size_t)n * K_ + k0_ + 8) * C_ + c) = o1;
        }
        r0 += __shfl_xor_sync(0xffffffffu, r0, 1);
        r0 += __shfl_xor_sync(0xffffffffu, r0, 2);
        r1 += __shfl_xor_sync(0xffffffffu, r1, 1);
        r1 += __shfl_xor_sync(0xffffffffu, r1, 2);
        if (t4 == 0) {
            atomicAdd(&g_rss[n * K_ + k0_], r0);
            atomicAdd(&g_rss[n * K_ + k0_ + 8], r1);
        }
    }
}

// ---------------------------------------------------------------------------
// K2b: per-row final scale. grid 32 x 64.
// ---------------------------------------------------------------------------
__global__ __launch_bounds__(64) void k2b_scale() {
    int n = blockIdx.x, k = threadIdx.x;
    float tot = g_rss[n * K_ + k];
    float rinv = 1.0f / fmaxf(sqrtf(tot), EPSF);
    float contrib = tot * rinv * rinv;
    float s = contrib;
#pragma unroll
    for (int o = 16; o; o >>= 1) s += __shfl_xor_sync(0xffffffffu, s, o);
    __shared__ float w2[2];
    if ((k & 31) == 0) w2[k >> 5] = s;
    __syncthreads();
    float nss = w2[0] + w2[1];
    g_scale[n * K_ + k] = rinv / fmaxf(sqrtf(nss), EPSF);
}

// ---------------------------------------------------------------------------
// K3: single streaming normalization pass. grid (64, 32), 128 thr, float4.
// ---------------------------------------------------------------------------
__global__ __launch_bounds__(128) void k3_norm(float* __restrict__ out) {
    int n = blockIdx.y, k = blockIdx.x, t = threadIdx.x;
    float sc = g_scale[n * K_ + k];
    float4* row = (float4*)(out + (size_t)n * (K_ * C_) + (size_t)k * C_);
    float4 v = row[t];
    v.x *= sc; v.y *= sc; v.z *= sc; v.w *= sc;
    row[t] = v;
}

// ---------------------------------------------------------------------------
extern "C" void kernel_launch(void* const* d_in, const int* in_sizes, int n_in,
                              void* d_out, int out_size) {
    const float* x = (const float*)d_in[0];
    const float* vocabs = (const float*)d_in[1];
    if (n_in >= 2 && in_sizes[0] == K_ * C_ && in_sizes[1] == N_ * C_ * P_) {
        vocabs = (const float*)d_in[0];
        x = (const float*)d_in[1];
    }
    float* out = (float*)d_out;

    k_init<<<2, 256>>>(vocabs);
    k1_assign<<<dim3(8, 32), 128>>>(x, vocabs);
    k2_vlad<<<dim3(8, 32), 128>>>(x, vocabs, out);
    k2b_scale<<<32, 64>>>();
    k3_norm<<<dim3(64, 32), 128>>>(out);
}

// round 10
// speedup vs baseline: 4.0873x; 1.1154x over previous
#include <cuda_runtime.h>
#include <cuda_fp16.h>
#include <cuda_bf16.h>
#include <math.h>

#define N_ 32
#define C_ 512
#define P_ 1024
#define K_ 64
#define ALPHAF 100.0f
#define EPSF 1e-12f
#define MSCALE 2048.0f
#define INV_MSCALE 4.8828125e-4f

typedef unsigned int u32;
typedef unsigned short u16;

// ---------------- scratch (no init required) ---------------------------------
__device__ float g_asum8[N_ * 8 * K_];        // per-(n, p-tile) asum slices
__device__ float g_rss8[N_ * 8 * K_];         // per-(n, c-tile) row-sumsq slices
__device__ u16 g_abf[(size_t)N_ * K_ * P_];   // bf16 of a*invn

// ---------------- helpers ----------------------------------------------------
__device__ __forceinline__ u32 smem_u32(const void* p) {
    u32 a;
    asm("{ .reg .u64 t; cvta.to.shared.u64 t, %1; cvt.u32.u64 %0, t; }" : "=r"(a) : "l"(p));
    return a;
}
__device__ __forceinline__ void ldsm4(u32* r, u32 addr) {
    asm volatile("ldmatrix.sync.aligned.m8n8.x4.shared.b16 {%0,%1,%2,%3}, [%4];"
                 : "=r"(r[0]), "=r"(r[1]), "=r"(r[2]), "=r"(r[3]) : "r"(addr));
}
__device__ __forceinline__ void ldsm4t(u32* r, u32 addr) {
    asm volatile("ldmatrix.sync.aligned.m8n8.x4.trans.shared.b16 {%0,%1,%2,%3}, [%4];"
                 : "=r"(r[0]), "=r"(r[1]), "=r"(r[2]), "=r"(r[3]) : "r"(addr));
}
__device__ __forceinline__ void mma16816(float* d, const u32* a, const u32* b) {
    asm volatile(
        "mma.sync.aligned.m16n8k16.row.col.f32.f16.f16.f32 "
        "{%0,%1,%2,%3}, {%4,%5,%6,%7}, {%8,%9}, {%0,%1,%2,%3};"
        : "+f"(d[0]), "+f"(d[1]), "+f"(d[2]), "+f"(d[3])
        : "r"(a[0]), "r"(a[1]), "r"(a[2]), "r"(a[3]), "r"(b[0]), "r"(b[1]));
}
__device__ __forceinline__ void mma16816bf(float* d, const u32* a, const u32* b) {
    asm volatile(
        "mma.sync.aligned.m16n8k16.row.col.f32.bf16.bf16.f32 "
        "{%0,%1,%2,%3}, {%4,%5,%6,%7}, {%8,%9}, {%0,%1,%2,%3};"
        : "+f"(d[0]), "+f"(d[1]), "+f"(d[2]), "+f"(d[3])
        : "r"(a[0]), "r"(a[1]), "r"(a[2]), "r"(a[3]), "r"(b[0]), "r"(b[1]));
}
__device__ __forceinline__ void split2(float v, u32& hbits, u32& mbits) {
    __half h = __float2half_rn(v);
    __half m = __float2half_rn((v - __half2float(h)) * MSCALE);
    hbits = (u32)__half_as_ushort(h);
    mbits = (u32)__half_as_ushort(m);
}

// ---------------------------------------------------------------------------
// K1: logits D[k=64, p=128] = sum_c (2a*w)[k,c]*x[c,p]. On-the-fly fp16
// 2-plane split from fp32; per-p sumsq -> invn in smem; bias computed in-block
// from w sumsq; asum written as per-block slice (no atomics).
// grid (8,32), 128 thr. smem 48KB: WH 8K | WM 8K | XH 16K | XM 16K.
// ---------------------------------------------------------------------------
__global__ __launch_bounds__(128) void k1_assign(const float* __restrict__ x,
                                                 const float* __restrict__ vocabs) {
    __shared__ __align__(16) char sm[49152];
    u32 sb = smem_u32(sm);
    const u32 WH = sb, WM = sb + 8192, XH = sb + 16384, XM = sb + 32768;
    float* ssacc = (float*)sm;            // [0,128)   post-mainloop
    float* sbias = (float*)sm + 128;      // [128,192)
    float* sasum = (float*)sm + 192;      // [192,448)

    int t = threadIdx.x;
    int warp = t >> 5, lane = t & 31;
    int g = lane >> 2, t4 = lane & 3;
    int jA = lane >> 3, rA = lane & 7;
    int n = blockIdx.y, p0 = blockIdx.x * 128;
    int pw = warp * 32;

    float dh[4][4][4], dl[4][4][4];
#pragma unroll
    for (int a = 0; a < 4; a++)
#pragma unroll
        for (int b = 0; b < 4; b++)
#pragma unroll
            for (int q = 0; q < 4; q++) { dh[a][b][q] = 0.0f; dl[a][b][q] = 0.0f; }

    const float* xb = x + (size_t)n * C_ * P_ + p0;
    int px = 2 * (t & 63);
    int cpar = t >> 6;
    int nbx = px >> 3;
    float ssx = 0.0f, ssy = 0.0f;
    float wacc[16];
#pragma unroll
    for (int i = 0; i < 16; i++) wacc[i] = 0.0f;

    for (int ch = 0; ch < 8; ch++) {
        int c0 = ch * 64;
        __syncthreads();
        // stage w (accumulate raw sumsq for bias)
        {
            int cp = t & 31;
            int c = 2 * cp, cb = c >> 3;
#pragma unroll
            for (int i = 0; i < 16; i++) {
                int k = warp + 4 * i;
                float2 v = *(const float2*)(vocabs + k * C_ + c0 + c);
                wacc[i] = fmaf(v.x, v.x, fmaf(v.y, v.y, wacc[i]));
                v.x *= 2.0f * ALPHAF; v.y *= 2.0f * ALPHAF;
                u32 hx, mx_, hy, my_;
                split2(v.x, hx, mx_);
                split2(v.y, hy, my_);
                u32 addr = (u32)(k * 128) + (((u32)cb ^ (u32)(k & 7)) << 4) + (c & 7) * 2;
                *(u32*)(sm + addr) = hx | (hy << 16);
                *(u32*)(sm + 8192 + addr) = mx_ | (my_ << 16);
            }
        }
        // stage x, accumulate per-p sumsq
#pragma unroll
        for (int i = 0; i < 32; i++) {
            int cc = cpar + 2 * i;
            float2 v = *(const float2*)(xb + (size_t)(c0 + cc) * P_ + px);
            ssx = fmaf(v.x, v.x, ssx);
            ssy = fmaf(v.y, v.y, ssy);
            u32 hx, mx_, hy, my_;
            split2(v.x, hx, mx_);
            split2(v.y, hy, my_);
            u32 off = (u32)(cc * 256) + (((u32)nbx ^ (u32)(cc & 7)) << 4) + (px & 7) * 2;
            *(u32*)(sm + 16384 + off) = hx | (hy << 16);
            *(u32*)(sm + 32768 + off) = mx_ | (my_ << 16);
        }
        __syncthreads();

#pragma unroll
        for (int ks = 0; ks < 4; ks++) {
            u32 Ah[4][4], Am[4][4], Bh[2][4], Bm[2][4];
#pragma unroll
            for (int mi = 0; mi < 4; mi++) {
                int k = mi * 16 + ((jA & 1) << 3) + rA;
                int cb = ks * 2 + (jA >> 1);
                u32 addr = (u32)(k * 128) + (((u32)cb ^ (u32)(k & 7)) << 4);
                ldsm4(Ah[mi], WH + addr);
                ldsm4(Am[mi], WM + addr);
            }
#pragma unroll
            for (int ni = 0; ni < 2; ni++) {
                int c = ks * 16 + ((jA & 1) << 3) + rA;
                int nb = warp * 4 + ni * 2 + (jA >> 1);
                u32 off = (u32)(c * 256) + (((u32)nb ^ (u32)(c & 7)) << 4);
                ldsm4t(Bh[ni], XH + off);
                ldsm4t(Bm[ni], XM + off);
            }
#pragma unroll
            for (int mi = 0; mi < 4; mi++)
#pragma unroll
                for (int ni = 0; ni < 2; ni++)
#pragma unroll
                    for (int nh = 0; nh < 2; nh++) {
                        mma16816(dh[mi][ni * 2 + nh], Ah[mi], &Bh[ni][nh * 2]);
                        mma16816(dl[mi][ni * 2 + nh], Ah[mi], &Bm[ni][nh * 2]);
                        mma16816(dl[mi][ni * 2 + nh], Am[mi], &Bh[ni][nh * 2]);
                    }
        }
    }

    // ---- post-mainloop reductions into reused smem ----
    __syncthreads();
    ssacc[t] = 0.0f;
    __syncthreads();
    atomicAdd(&ssacc[px], ssx);
    atomicAdd(&ssacc[px + 1], ssy);
    // bias: warp-reduce wacc (each warp owns k = warp + 4i)
#pragma unroll
    for (int i = 0; i < 16; i++) {
        float s = wacc[i];
#pragma unroll
        for (int o = 16; o; o >>= 1) s += __shfl_xor_sync(0xffffffffu, s, o);
        if (lane == 0) sbias[warp + 4 * i] = -ALPHAF * sqrtf(s);
    }
    __syncthreads();

    float d[4][4][4];
#pragma unroll
    for (int mi = 0; mi < 4; mi++)
#pragma unroll
        for (int nj = 0; nj < 4; nj++)
#pragma unroll
            for (int q = 0; q < 4; q++)
                d[mi][nj][q] = fmaf(dl[mi][nj][q], INV_MSCALE, dh[mi][nj][q]);

    float invp[4][2], bias[4][2];
#pragma unroll
    for (int nj = 0; nj < 4; nj++) {
        int pl = pw + nj * 8 + 2 * t4;
        invp[nj][0] = 1.0f / fmaxf(sqrtf(ssacc[pl]), EPSF);
        invp[nj][1] = 1.0f / fmaxf(sqrtf(ssacc[pl + 1]), EPSF);
    }
#pragma unroll
    for (int mi = 0; mi < 4; mi++) {
        bias[mi][0] = sbias[mi * 16 + g];
        bias[mi][1] = sbias[mi * 16 + g + 8];
    }
    float lg[4][4][4];
    float mx[4][2];
#pragma unroll
    for (int nj = 0; nj < 4; nj++) { mx[nj][0] = -1e30f; mx[nj][1] = -1e30f; }
#pragma unroll
    for (int mi = 0; mi < 4; mi++)
#pragma unroll
        for (int nj = 0; nj < 4; nj++) {
            lg[mi][nj][0] = fmaf(d[mi][nj][0], invp[nj][0], bias[mi][0]);
            lg[mi][nj][1] = fmaf(d[mi][nj][1], invp[nj][1], bias[mi][0]);
            lg[mi][nj][2] = fmaf(d[mi][nj][2], invp[nj][0], bias[mi][1]);
            lg[mi][nj][3] = fmaf(d[mi][nj][3], invp[nj][1], bias[mi][1]);
            mx[nj][0] = fmaxf(mx[nj][0], fmaxf(lg[mi][nj][0], lg[mi][nj][2]));
            mx[nj][1] = fmaxf(mx[nj][1], fmaxf(lg[mi][nj][1], lg[mi][nj][3]));
        }
#pragma unroll
    for (int nj = 0; nj < 4; nj++)
#pragma unroll
        for (int cc = 0; cc < 2; cc++) {
            float m = mx[nj][cc];
#pragma unroll
            for (int o = 4; o <= 16; o <<= 1) m = fmaxf(m, __shfl_xor_sync(0xffffffffu, m, o));
            mx[nj][cc] = m;
        }
    float sx[4][2];
#pragma unroll
    for (int nj = 0; nj < 4; nj++) { sx[nj][0] = 0.0f; sx[nj][1] = 0.0f; }
#pragma unroll
    for (int mi = 0; mi < 4; mi++)
#pragma unroll
        for (int nj = 0; nj < 4; nj++) {
            lg[mi][nj][0] = __expf(lg[mi][nj][0] - mx[nj][0]);
            lg[mi][nj][1] = __expf(lg[mi][nj][1] - mx[nj][1]);
            lg[mi][nj][2] = __expf(lg[mi][nj][2] - mx[nj][0]);
            lg[mi][nj][3] = __expf(lg[mi][nj][3] - mx[nj][1]);
            sx[nj][0] += lg[mi][nj][0] + lg[mi][nj][2];
            sx[nj][1] += lg[mi][nj][1] + lg[mi][nj][3];
        }
#pragma unroll
    for (int nj = 0; nj < 4; nj++)
#pragma unroll
        for (int cc = 0; cc < 2; cc++) {
            float s = sx[nj][cc];
#pragma unroll
            for (int o = 4; o <= 16; o <<= 1) s += __shfl_xor_sync(0xffffffffu, s, o);
            sx[nj][cc] = 1.0f / s;
        }
    float asl[4][2];
#pragma unroll
    for (int mi = 0; mi < 4; mi++) { asl[mi][0] = 0.0f; asl[mi][1] = 0.0f; }
    u16* ab = g_abf + (size_t)n * K_ * P_;
#pragma unroll
    for (int mi = 0; mi < 4; mi++)
#pragma unroll
        for (int nj = 0; nj < 4; nj++) {
            int p = p0 + pw + nj * 8 + 2 * t4;
            int k0_ = mi * 16 + g;
            float a00 = lg[mi][nj][0] * sx[nj][0];
            float a01 = lg[mi][nj][1] * sx[nj][1];
            float a10 = lg[mi][nj][2] * sx[nj][0];
            float a11 = lg[mi][nj][3] * sx[nj][1];
            asl[mi][0] += a00 + a01;
            asl[mi][1] += a10 + a11;
            u32 w0 = (u32)__bfloat16_as_ushort(__float2bfloat16(a00 * invp[nj][0])) |
                     ((u32)__bfloat16_as_ushort(__float2bfloat16(a01 * invp[nj][1])) << 16);
            u32 w1 = (u32)__bfloat16_as_ushort(__float2bfloat16(a10 * invp[nj][0])) |
                     ((u32)__bfloat16_as_ushort(__float2bfloat16(a11 * invp[nj][1])) << 16);
            *(u32*)(ab + (size_t)k0_ * P_ + p) = w0;
            *(u32*)(ab + (size_t)(k0_ + 8) * P_ + p) = w1;
        }
    // per-warp asum partials -> smem, then block sum -> slice (no atomics)
#pragma unroll
    for (int mi = 0; mi < 4; mi++)
#pragma unroll
        for (int h = 0; h < 2; h++) {
            float s = asl[mi][h];
            s += __shfl_xor_sync(0xffffffffu, s, 1);
            s += __shfl_xor_sync(0xffffffffu, s, 2);
            if (t4 == 0) sasum[warp * 64 + mi * 16 + g + 8 * h] = s;
        }
    __syncthreads();
    if (t < 64) {
        float s = sasum[t] + sasum[64 + t] + sasum[128 + t] + sasum[192 + t];
        g_asum8[(n * 8 + blockIdx.x) * K_ + t] = s;
    }
}

// ---------------------------------------------------------------------------
// K2: vlad D[k=64, c=64] = sum_p atil[k,p]*x[c,p] via bf16 mma; asum summed
// from slices; rss written as per-block slice. grid (8,32), 128 thr.
// smem 32KB: AS 16K | XS 16K (256B swizzled rows).
// ---------------------------------------------------------------------------
__global__ __launch_bounds__(128) void k2_vlad(const float* __restrict__ x,
                                               const float* __restrict__ vocabs,
                                               float* __restrict__ out) {
    __shared__ __align__(16) char sm[32768];
    u32 sb = smem_u32(sm);
    const u32 AS = sb, XS = sb + 16384;
    float* srss = (float*)sm;   // reused post-mainloop

    int t = threadIdx.x;
    int warp = t >> 5, lane = t & 31;
    int g = lane >> 2, t4 = lane & 3;
    int jA = lane >> 3, rA = lane & 7;
    int n = blockIdx.y, c0 = blockIdx.x * 64;

    float d[4][2][4];
#pragma unroll
    for (int a = 0; a < 4; a++)
#pragma unroll
        for (int b = 0; b < 2; b++)
#pragma unroll
            for (int q = 0; q < 4; q++) d[a][b][q] = 0.0f;

    const u16* ab = g_abf + (size_t)n * K_ * P_;
    const float* xb = x + (size_t)n * C_ * P_;

    for (int ch = 0; ch < 8; ch++) {
        int p0 = ch * 128;
        __syncthreads();
#pragma unroll
        for (int i = 0; i < 32; i++) {
            int q = t + 128 * i;
            int k = q >> 6, pp = q & 63;
            int p = 2 * pp;
            u32 e = *(const u32*)(ab + (size_t)k * P_ + p0 + p);
            u32 addr = (u32)(k * 256) + ((((u32)(p >> 3)) ^ (u32)(k & 7)) << 4) + (p & 7) * 2;
            *(u32*)(sm + addr) = e;
        }
#pragma unroll
        for (int i = 0; i < 32; i++) {
            int q = t + 128 * i;
            int cr = q >> 6, pp = q & 63;
            int p = 2 * pp;
            float2 v = *(const float2*)(xb + (size_t)(c0 + cr) * P_ + p0 + p);
            __nv_bfloat162 b2 = __float22bfloat162_rn(v);
            u32 val = *reinterpret_cast<u32*>(&b2);
            u32 addr = 16384u + (u32)(cr * 256) + ((((u32)(p >> 3)) ^ (u32)(cr & 7)) << 4) + (p & 7) * 2;
            *(u32*)(sm + addr) = val;
        }
        __syncthreads();

#pragma unroll
        for (int ks = 0; ks < 8; ks++) {
            u32 Ah[4][4], Bh[4];
#pragma unroll
            for (int mi = 0; mi < 4; mi++) {
                int k = mi * 16 + ((jA & 1) << 3) + rA;
                u32 pbv = (u32)(ks * 2 + (jA >> 1));
                ldsm4(Ah[mi], AS + k * 256 + ((pbv ^ (u32)(k & 7)) << 4));
            }
            {
                int cr = warp * 16 + ((jA >> 1) << 3) + rA;
                u32 pbv = (u32)(ks * 2 + (jA & 1));
                ldsm4(Bh, XS + cr * 256 + ((pbv ^ (u32)(cr & 7)) << 4));
            }
#pragma unroll
            for (int mi = 0; mi < 4; mi++)
#pragma unroll
                for (int nh = 0; nh < 2; nh++)
                    mma16816bf(d[mi][nh], Ah[mi], &Bh[nh * 2]);
        }
    }

    __syncthreads();   // smem reuse for rss partials
#pragma unroll
    for (int mi = 0; mi < 4; mi++) {
        int k0_ = mi * 16 + g;
        float s0 = 0.0f, s1 = 0.0f;
#pragma unroll
        for (int pt = 0; pt < 8; pt++) {
            s0 += g_asum8[(n * 8 + pt) * K_ + k0_];
            s1 += g_asum8[(n * 8 + pt) * K_ + k0_ + 8];
        }
        float r0 = 0.0f, r1 = 0.0f;
#pragma unroll
        for (int nb = 0; nb < 2; nb++) {
            int c = c0 + warp * 16 + nb * 8 + 2 * t4;
            float2 v0 = *(const float2*)(vocabs + k0_ * C_ + c);
            float2 v1 = *(const float2*)(vocabs + (k0_ + 8) * C_ + c);
            float2 o0, o1;
            o0.x = fmaf(-s0, v0.x, d[mi][nb][0]);
            o0.y = fmaf(-s0, v0.y, d[mi][nb][1]);
            o1.x = fmaf(-s1, v1.x, d[mi][nb][2]);
            o1.y = fmaf(-s1, v1.y, d[mi][nb][3]);
            r0 += o0.x * o0.x + o0.y * o0.y;
            r1 += o1.x * o1.x + o1.y * o1.y;
            *(float2*)(out + ((size_t)n * K_ + k0_) * C_ + c) = o0;
            *(float2*)(out + ((size_t)n * K_ + k0_ + 8) * C_ + c) = o1;
        }
        r0 += __shfl_xor_sync(0xffffffffu, r0, 1);
        r0 += __shfl_xor_sync(0xffffffffu, r0, 2);
        r1 += __shfl_xor_sync(0xffffffffu, r1, 1);
        r1 += __shfl_xor_sync(0xffffffffu, r1, 2);
        if (t4 == 0) {
            srss[warp * 64 + k0_] = r0;
            srss[warp * 64 + k0_ + 8] = r1;
        }
    }
    __syncthreads();
    if (t < 64) {
        float s = srss[t] + srss[64 + t] + srss[128 + t] + srss[192 + t];
        g_rss8[(n * 8 + blockIdx.x) * K_ + t] = s;
    }
}

// ---------------------------------------------------------------------------
// K3: fused scale computation + streaming normalization. grid (64, 32), 128 thr.
// ---------------------------------------------------------------------------
__global__ __launch_bounds__(128) void k3_norm(float* __restrict__ out) {
    int n = blockIdx.y, k = blockIdx.x, t = threadIdx.x;
    __shared__ float srinv[64];
    __shared__ float sns[2];
    float contrib = 0.0f;
    if (t < 64) {
        float tot = 0.0f;
#pragma unroll
        for (int ct = 0; ct < 8; ct++) tot += g_rss8[(n * 8 + ct) * K_ + t];
        float rinv = 1.0f / fmaxf(sqrtf(tot), EPSF);
        srinv[t] = rinv;
        contrib = tot * rinv * rinv;
    }
    // reduce contrib over threads 0..63 (2 warps)
    float s = contrib;
#pragma unroll
    for (int o = 16; o; o >>= 1) s += __shfl_xor_sync(0xffffffffu, s, o);
    if (t < 64 && (t & 31) == 0) sns[t >> 5] = s;
    __syncthreads();
    float sc = srinv[k] / fmaxf(sqrtf(sns[0] + sns[1]), EPSF);
    float4* row = (float4*)(out + (size_t)n * (K_ * C_) + (size_t)k * C_);
    float4 v = row[t];
    v.x *= sc; v.y *= sc; v.z *= sc; v.w *= sc;
    row[t] = v;
}

// ---------------------------------------------------------------------------
extern "C" void kernel_launch(void* const* d_in, const int* in_sizes, int n_in,
                              void* d_out, int out_size) {
    const float* x = (const float*)d_in[0];
    const float* vocabs = (const float*)d_in[1];
    if (n_in >= 2 && in_sizes[0] == K_ * C_ && in_sizes[1] == N_ * C_ * P_) {
        vocabs = (const float*)d_in[0];
        x = (const float*)d_in[1];
    }
    float* out = (float*)d_out;

    k1_assign<<<dim3(8, 32), 128>>>(x, vocabs);
    k2_vlad<<<dim3(8, 32), 128>>>(x, vocabs, out);
    k3_norm<<<dim3(64, 32), 128>>>(out);
}